// round 12
// baseline (speedup 1.0000x reference)
#include <cuda_runtime.h>
#include <cuda_bf16.h>
#include <math.h>
#include <stdint.h>

#define HID   1152
#define NH    16
#define HD    72
#define TXT   256
#define BATCH 8
#define SEQ   1280
#define TOK   (BATCH*SEQ)   /* 10240 */
#define EPS   1e-6f

typedef __nv_bfloat16 bf16;

extern __shared__ char dynsmem[];

// ---------------- scratch ----------------------------------------------------
__device__ float g_mod [BATCH*6*HID];
__device__ float g_qkv [TOK*3*HID];
__device__ bf16  g_qkvh[TOK*3*HID], g_qkvl[TOK*3*HID];
__device__ float g_res32 [TOK*HID];
__device__ float g_attn32[TOK*HID];
__device__ float g_h32   [TOK*4*HID];
// tf32-rounded, TRANSPOSED weights: [N][K]
__device__ float g_wqkvT[3*HID*HID];
__device__ float g_wprojT[HID*HID];
__device__ float g_wm1T[4*HID*HID];
__device__ float g_wm2T[HID*4*HID];

// ---------------- helpers ----------------------------------------------------
__device__ __forceinline__ float tf32r(float x) {
    unsigned u; asm("cvt.rna.tf32.f32 %0, %1;" : "=r"(u) : "f"(x));
    return __uint_as_float(u);
}
__device__ __forceinline__ void split1(float x, bf16 &h, bf16 &l) {
    h = __float2bfloat16_rn(x);
    l = __float2bfloat16_rn(x - __bfloat162float(h));
}
__device__ __forceinline__ unsigned packh2(float a, float b) {
    __nv_bfloat16 ha = __float2bfloat16_rn(a), hb = __float2bfloat16_rn(b);
    return (unsigned)__bfloat16_as_ushort(ha) |
           ((unsigned)__bfloat16_as_ushort(hb) << 16);
}
__device__ __forceinline__ unsigned packl2(float a, float b) {
    float ra = a - __bfloat162float(__float2bfloat16_rn(a));
    float rb = b - __bfloat162float(__float2bfloat16_rn(b));
    return packh2(ra, rb);
}
__device__ __forceinline__ unsigned su32(const void* p) {
    return (unsigned)__cvta_generic_to_shared(p);
}
__device__ __forceinline__ void cp16(unsigned dst, const void* src) {
    asm volatile("cp.async.ca.shared.global [%0],[%1],16;\n" :: "r"(dst), "l"(src));
}
__device__ __forceinline__ void cp16cg(unsigned dst, const void* src) {
    asm volatile("cp.async.cg.shared.global [%0],[%1],16;\n" :: "r"(dst), "l"(src));
}
__device__ __forceinline__ void cpcommit() {
    asm volatile("cp.async.commit_group;\n");
}
template<int N_> __device__ __forceinline__ void cpwait() {
    asm volatile("cp.async.wait_group %0;\n" :: "n"(N_));
}
__device__ __forceinline__ void ldsm4(unsigned* r, unsigned a)
{
    asm volatile("ldmatrix.sync.aligned.m8n8.x4.shared.b16 {%0,%1,%2,%3},[%4];\n"
                 : "=r"(r[0]), "=r"(r[1]), "=r"(r[2]), "=r"(r[3]) : "r"(a));
}
__device__ __forceinline__ void ldsm4t(unsigned* r, unsigned a)
{
    asm volatile("ldmatrix.sync.aligned.m8n8.x4.trans.shared.b16 {%0,%1,%2,%3},[%4];\n"
                 : "=r"(r[0]), "=r"(r[1]), "=r"(r[2]), "=r"(r[3]) : "r"(a));
}
__device__ __forceinline__ void mma16816(float* c, const unsigned* a, const unsigned* b)
{
    asm volatile("mma.sync.aligned.m16n8k16.row.col.f32.bf16.bf16.f32 "
                 "{%0,%1,%2,%3},{%4,%5,%6,%7},{%8,%9},{%0,%1,%2,%3};\n"
                 : "+f"(c[0]), "+f"(c[1]), "+f"(c[2]), "+f"(c[3])
                 : "r"(a[0]), "r"(a[1]), "r"(a[2]), "r"(a[3]),
                   "r"(b[0]), "r"(b[1]));
}
__device__ __forceinline__ void mmatf32u(float* c, const unsigned* a, const unsigned* b)
{
    asm volatile("mma.sync.aligned.m16n8k8.row.col.f32.tf32.tf32.f32 "
                 "{%0,%1,%2,%3},{%4,%5,%6,%7},{%8,%9},{%0,%1,%2,%3};\n"
                 : "+f"(c[0]), "+f"(c[1]), "+f"(c[2]), "+f"(c[3])
                 : "r"(a[0]), "r"(a[1]), "r"(a[2]), "r"(a[3]),
                   "r"(b[0]), "r"(b[1]));
}
__device__ __forceinline__ float gelu_tanh(float t) {
    return 0.5f*t*(1.f + tanhf(0.7978845608028654f*(t + 0.044715f*t*t*t)));
}

// ---------------- merged weight transpose + tf32 round -----------------------
#define TQ1 ((3*HID/32)*(HID/32))
#define TQ2 (TQ1 + (HID/32)*(HID/32))
#define TQ3 (TQ2 + (4*HID/32)*(HID/32))
#define TQ4 (TQ3 + (HID/32)*(4*HID/32))
__global__ void k_roundwT(const float* __restrict__ w_qkv,
                          const float* __restrict__ w_proj,
                          const float* __restrict__ w_mlp1,
                          const float* __restrict__ w_mlp2)
{
    __shared__ float tile[32][33];
    int bid = blockIdx.x;
    const float* src; float* dst; int K, N, li;
    if (bid < TQ1)      { src = w_qkv;  dst = g_wqkvT;  K = HID;   N = 3*HID; li = bid; }
    else if (bid < TQ2) { src = w_proj; dst = g_wprojT; K = HID;   N = HID;   li = bid - TQ1; }
    else if (bid < TQ3) { src = w_mlp1; dst = g_wm1T;   K = HID;   N = 4*HID; li = bid - TQ2; }
    else                { src = w_mlp2; dst = g_wm2T;   K = 4*HID; N = HID;   li = bid - TQ3; }
    int ntN = N / 32;
    int nb = (li % ntN) * 32, kb = (li / ntN) * 32;
    int tx = threadIdx.x, ty = threadIdx.y;
    #pragma unroll
    for (int i = 0; i < 4; i++)
        tile[ty + i*8][tx] = src[(size_t)(kb + ty + i*8)*N + nb + tx];
    __syncthreads();
    #pragma unroll
    for (int i = 0; i < 4; i++)
        dst[(size_t)(nb + ty + i*8)*K + kb + tx] = tf32r(tile[tx][ty + i*8]);
}

// ---------------- adaLN ------------------------------------------------------
__global__ void k_ada(const float* __restrict__ c,
                      const float* __restrict__ w,
                      const float* __restrict__ bias)
{
    __shared__ float sc[HID];
    int b = blockIdx.y;
    for (int i = threadIdx.x; i < HID; i += blockDim.x) {
        float v = c[b*HID + i];
        sc[i] = v / (1.f + __expf(-v));
    }
    __syncthreads();
    int n = blockIdx.x*128 + threadIdx.x;
    float acc = bias[n];
    #pragma unroll 4
    for (int k = 0; k < HID; k++) acc += sc[k] * w[(size_t)k*(6*HID) + n];
    g_mod[b*6*HID + n] = acc;
}

// ---------------- fused LN + modulate, writes tf32-rounded fp32 --------------
__global__ void k_lnmod(const float* __restrict__ x, float* __restrict__ o32,
                        int shofs, int scofs)
{
    int row = blockIdx.x;
    int b   = row / SEQ;
    int t   = threadIdx.x;
    float4 v = ((const float4*)(x + (size_t)row*HID))[t];
    float s  = v.x + v.y + v.z + v.w;
    float ss = v.x*v.x + v.y*v.y + v.z*v.z + v.w*v.w;
    #pragma unroll
    for (int off = 16; off >= 1; off >>= 1) {
        s  += __shfl_xor_sync(0xffffffffu, s , off);
        ss += __shfl_xor_sync(0xffffffffu, ss, off);
    }
    __shared__ float rs[9], rss[9];
    __shared__ float smu, srs;
    if ((t & 31) == 0) { rs[t>>5] = s; rss[t>>5] = ss; }
    __syncthreads();
    if (t == 0) {
        float S = 0.f, SS = 0.f;
        #pragma unroll
        for (int i = 0; i < 9; i++) { S += rs[i]; SS += rss[i]; }
        float mu  = S * (1.f/(float)HID);
        float var = SS * (1.f/(float)HID) - mu*mu;
        smu = mu; srs = rsqrtf(var + EPS);
    }
    __syncthreads();
    float mu = smu, r = srs;
    float4 sh = ((const float4*)(g_mod + b*6*HID + shofs))[t];
    float4 sc = ((const float4*)(g_mod + b*6*HID + scofs))[t];
    float4 o;
    o.x = tf32r((1.f+sc.x)*((v.x-mu)*r) + sh.x);
    o.y = tf32r((1.f+sc.y)*((v.y-mu)*r) + sh.y);
    o.z = tf32r((1.f+sc.z)*((v.z-mu)*r) + sh.z);
    o.w = tf32r((1.f+sc.w)*((v.w-mu)*r) + sh.w);
    ((float4*)(o32 + (size_t)row*HID))[t] = o;
}

// ---------------- tf32 GEMM, 256x128 tile, 512 threads, frag dbl-buffered ----
#define BKF 32
#define APADF 36
#define BPADF 36
#define SMAF (256*APADF)
#define SMBF (128*BPADF)
#define GSMEM (3*(SMAF+SMBF)*4)
__global__ __launch_bounds__(512, 1)
void k_gemm32(const float* __restrict__ A, const float* __restrict__ B,
              const float* __restrict__ bias,
              float* C, float* C2,
              int M, int N, int K, int mode, const float* xres, int gofs)
{
    float* smem = (float*)dynsmem;
    const int t    = threadIdx.x;
    const int lane = t & 31;
    const int wid  = t >> 5;                 // 0..15
    const int m0   = blockIdx.y * 256;
    const int n0   = blockIdx.x * 128;
    const int wm   = (wid >> 2) * 64;        // 0,64,128,192
    const int wn   = (wid & 3) * 32;         // 0,32,64,96
    const int lq   = lane >> 2;
    const int lm   = lane & 3;

    const int a_ro = (lane & 7) + ((lane >> 3) & 1) * 8;
    const int a_co = (lane >> 4) * 4;
    const int b_ro = (lane & 7) + ((lane >> 4) & 1) * 8;
    const int b_co = ((lane >> 3) & 1) * 4;

    float acc[4][4][4];
    #pragma unroll
    for (int i = 0; i < 4; i++)
        #pragma unroll
        for (int j = 0; j < 4; j++)
            #pragma unroll
            for (int q = 0; q < 4; q++) acc[i][j][q] = 0.f;

    const int nIter = K / BKF;

    auto issue = [&](int it, int s) {
        float* as = smem + s*(SMAF + SMBF);
        float* bs = as + SMAF;
        int k0 = it * BKF;
        #pragma unroll
        for (int j = 0; j < 4; j++) {                 // A: 2048 cp16
            int cch = t + j*512;
            int r = cch >> 3, c4 = (cch & 7)*4;
            cp16cg(su32(as + r*APADF + c4), A + (size_t)(m0 + r)*K + k0 + c4);
        }
        #pragma unroll
        for (int j = 0; j < 2; j++) {                 // B: 1024 cp16
            int cch = t + j*512;
            int r = cch >> 3, c4 = (cch & 7)*4;
            cp16cg(su32(bs + r*BPADF + c4), B + (size_t)(n0 + r)*K + k0 + c4);
        }
        cpcommit();
    };

    issue(0, 0);
    issue(1, 1);

    unsigned af[2][4][4], bf[2][2][4];

    for (int it = 0; it < nIter; it++) {
        if (it + 1 < nIter) cpwait<1>(); else cpwait<0>();
        __syncthreads();
        if (it + 2 < nIter) issue(it + 2, (it + 2) % 3);

        float* as = smem + (it % 3)*(SMAF + SMBF);
        float* bs = as + SMAF;

        #pragma unroll
        for (int mt = 0; mt < 4; mt++)
            ldsm4(af[0][mt], su32(as + (wm + mt*16 + a_ro)*APADF + a_co));
        #pragma unroll
        for (int bt = 0; bt < 2; bt++)
            ldsm4(bf[0][bt], su32(bs + (wn + bt*16 + b_ro)*BPADF + b_co));

        #pragma unroll
        for (int s8 = 0; s8 < 4; s8++) {
            int cur = s8 & 1, nxt = cur ^ 1;
            if (s8 < 3) {
                int ks = (s8 + 1) * 8;
                #pragma unroll
                for (int mt = 0; mt < 4; mt++)
                    ldsm4(af[nxt][mt],
                          su32(as + (wm + mt*16 + a_ro)*APADF + ks + a_co));
                #pragma unroll
                for (int bt = 0; bt < 2; bt++)
                    ldsm4(bf[nxt][bt],
                          su32(bs + (wn + bt*16 + b_ro)*BPADF + ks + b_co));
            }
            #pragma unroll
            for (int mt = 0; mt < 4; mt++)
                #pragma unroll
                for (int bt = 0; bt < 2; bt++) {
                    mmatf32u(acc[mt][bt*2],   af[cur][mt], &bf[cur][bt][0]);
                    mmatf32u(acc[mt][bt*2+1], af[cur][mt], &bf[cur][bt][2]);
                }
        }
    }

    // epilogue
    #pragma unroll
    for (int mt = 0; mt < 4; mt++) {
        #pragma unroll
        for (int half = 0; half < 2; half++) {
            int row = m0 + wm + mt*16 + lq + half*8;
            int bq  = row / SEQ;
            #pragma unroll
            for (int nt = 0; nt < 4; nt++) {
                int col = n0 + wn + nt*8 + lm*2;
                float2 bb = *(const float2*)(bias + col);
                float v0 = acc[mt][nt][half*2+0] + bb.x;
                float v1 = acc[mt][nt][half*2+1] + bb.y;
                if (mode == 1) {
                    float2 g  = *(const float2*)(g_mod + bq*6*HID + gofs + col);
                    float2 xr = *(const float2*)(xres + (size_t)row*N + col);
                    float2 o; o.x = xr.x + g.x*v0; o.y = xr.y + g.y*v1;
                    *(float2*)(C + (size_t)row*N + col) = o;
                } else if (mode == 2) {
                    float2 o;
                    o.x = tf32r(gelu_tanh(v0));
                    o.y = tf32r(gelu_tanh(v1));
                    *(float2*)(C2 + (size_t)row*N + col) = o;
                } else {
                    float2 o; o.x = v0; o.y = v1;
                    *(float2*)(C + (size_t)row*N + col) = o;
                }
            }
        }
    }
}

// ---------------- fused RoPE + scale + split: fp32 qkv -> bf16 hi/lo ---------
__global__ void k_ropesplit(const float* __restrict__ cosb,
                            const float* __restrict__ sinb)
{
    const float scale = 0.11785113019775793f;
    size_t i = (size_t)blockIdx.x*256 + threadIdx.x;
    size_t e = i*4;
    int row = (int)(e / (3*HID));
    int col = (int)(e % (3*HID));
    int pos = row % SEQ;
    int seg = col / HID;
    int d   = (col % HID) % HD;

    float4 v = ((const float4*)g_qkv)[i];
    float o[4] = {v.x, v.y, v.z, v.w};

    if (seg < 2 && pos >= TXT) {
        int p = pos - TXT;
        if (d < 36) {
            float4 v2 = *(const float4*)(g_qkv + e + 36);
            float w2[4] = {v2.x, v2.y, v2.z, v2.w};
            #pragma unroll
            for (int j = 0; j < 4; j++) {
                float cv = cosb[p*36 + d + j], sv = sinb[p*36 + d + j];
                o[j] = o[j]*cv - w2[j]*sv;
            }
        } else {
            float4 v1 = *(const float4*)(g_qkv + e - 36);
            float w1[4] = {v1.x, v1.y, v1.z, v1.w};
            #pragma unroll
            for (int j = 0; j < 4; j++) {
                float cv = cosb[p*36 + d - 36 + j], sv = sinb[p*36 + d - 36 + j];
                o[j] = w1[j]*sv + o[j]*cv;
            }
        }
    }
    if (seg == 0) {
        #pragma unroll
        for (int j = 0; j < 4; j++) o[j] *= scale;
    }
    bf16 hh[4], ll[4];
    split1(o[0], hh[0], ll[0]); split1(o[1], hh[1], ll[1]);
    split1(o[2], hh[2], ll[2]); split1(o[3], hh[3], ll[3]);
    ((uint2*)g_qkvh)[i] = *(uint2*)hh;
    ((uint2*)g_qkvl)[i] = *(uint2*)ll;
}

// ---------------- tensor-core flash attention (bf16x3, validated) ------------
#define ATSTR   88
#define TILE_Q  (128*ATSTR*2)
#define TILE_KV (64*ATSTR*2)
#define ATT_SMEM (2*TILE_Q + 2*4*TILE_KV)
__global__ __launch_bounds__(256)
void k_attn_tc(const bf16* __restrict__ qh, const bf16* __restrict__ ql,
               float* __restrict__ attn)
{
    char* smem = dynsmem;
    const unsigned sb    = su32(smem);
    const unsigned sQh   = sb;
    const unsigned sQl   = sb + TILE_Q;
    const unsigned sKV0  = sb + 2*TILE_Q;

    const int t    = threadIdx.x;
    const int lane = t & 31;
    const int wid  = t >> 5;
    const int q0   = blockIdx.x * 128;
    const int h    = blockIdx.y;
    const int b    = blockIdx.z;
    const int wm   = wid * 16;
    const int lrow = lane & 15;
    const int lcol = (lane >> 4) * 8;

    #pragma unroll
    for (int i = 0; i < ATT_SMEM/16/256; i++) {
        uint4 z = {0,0,0,0};
        *(uint4*)(smem + (i*256 + t)*16) = z;
    }
    __syncthreads();

    {
        #pragma unroll
        for (int rep = 0; rep < 9; rep++) {
            int id  = rep*256 + t;
            int op  = id / 1152;
            int rid = id % 1152;
            int row = rid / 9, c8 = rid % 9;
            const bf16* src = (op ? ql : qh)
                + (size_t)(b*SEQ + q0 + row)*(3*HID) + h*HD + c8*8;
            cp16((op ? sQl : sQh) + (row*ATSTR + c8*8)*2, src);
        }
        cpcommit();
    }

    auto stage_kv = [&](int kt, int s) {
        unsigned base = sKV0 + s*4*TILE_KV;
        #pragma unroll
        for (int rep = 0; rep < 9; rep++) {
            int id  = rep*256 + t;
            int op  = id / 576;
            int rid = id % 576;
            int row = rid / 9, c8 = rid % 9;
            const bf16* srcb = (op & 1) ? ql : qh;
            int seg = (op >> 1) ? 2*HID : HID;
            const bf16* src = srcb + (size_t)(b*SEQ + kt*64 + row)*(3*HID)
                            + seg + h*HD + c8*8;
            cp16(base + op*TILE_KV + (row*ATSTR + c8*8)*2, src);
        }
        cpcommit();
    };

    stage_kv(0, 0);

    float m0r = -3.0e38f, m1r = -3.0e38f, l0r = 0.f, l1r = 0.f;
    float o[10][4];
    #pragma unroll
    for (int i = 0; i < 10; i++)
        #pragma unroll
        for (int j = 0; j < 4; j++) o[i][j] = 0.f;

    const int NKV = SEQ/64;
    for (int kt = 0; kt < NKV; kt++) {
        cpwait<0>();
        __syncthreads();
        if (kt + 1 < NKV) stage_kv(kt + 1, (kt + 1) & 1);

        unsigned kvb = sKV0 + (kt & 1)*4*TILE_KV;
        unsigned sKh = kvb, sKl = kvb + TILE_KV;
        unsigned sVh = kvb + 2*TILE_KV, sVl = kvb + 3*TILE_KV;

        float s[8][4];
        #pragma unroll
        for (int i = 0; i < 8; i++)
            #pragma unroll
            for (int j = 0; j < 4; j++) s[i][j] = 0.f;

        #pragma unroll
        for (int kc = 0; kc < 5; kc++) {
            unsigned aH[4], aL[4];
            ldsm4(aH, sQh + ((wm + lrow)*ATSTR + kc*16 + lcol)*2);
            ldsm4(aL, sQl + ((wm + lrow)*ATSTR + kc*16 + lcol)*2);
            #pragma unroll
            for (int jt = 0; jt < 4; jt++) {
                unsigned kH[4], kL[4];
                ldsm4(kH, sKh + ((jt*16 + lrow)*ATSTR + kc*16 + lcol)*2);
                ldsm4(kL, sKl + ((jt*16 + lrow)*ATSTR + kc*16 + lcol)*2);
                unsigned bh0[2] = {kH[0], kH[2]}, bh1[2] = {kH[1], kH[3]};
                unsigned bl0[2] = {kL[0], kL[2]}, bl1[2] = {kL[1], kL[3]};
                mma16816(s[jt*2],   aH, bh0);
                mma16816(s[jt*2],   aL, bh0);
                mma16816(s[jt*2],   aH, bl0);
                mma16816(s[jt*2+1], aH, bh1);
                mma16816(s[jt*2+1], aL, bh1);
                mma16816(s[jt*2+1], aH, bl1);
            }
        }

        float tm0 = -3.0e38f, tm1 = -3.0e38f;
        #pragma unroll
        for (int f = 0; f < 8; f++) {
            tm0 = fmaxf(tm0, fmaxf(s[f][0], s[f][1]));
            tm1 = fmaxf(tm1, fmaxf(s[f][2], s[f][3]));
        }
        #pragma unroll
        for (int off = 1; off <= 2; off <<= 1) {
            tm0 = fmaxf(tm0, __shfl_xor_sync(0xffffffffu, tm0, off));
            tm1 = fmaxf(tm1, __shfl_xor_sync(0xffffffffu, tm1, off));
        }
        float nm0 = fmaxf(m0r, tm0), nm1 = fmaxf(m1r, tm1);
        float cf0 = __expf(m0r - nm0), cf1 = __expf(m1r - nm1);
        m0r = nm0; m1r = nm1;

        float rs0 = 0.f, rs1 = 0.f;
        #pragma unroll
        for (int f = 0; f < 8; f++) {
            s[f][0] = __expf(s[f][0] - nm0);
            s[f][1] = __expf(s[f][1] - nm0);
            s[f][2] = __expf(s[f][2] - nm1);
            s[f][3] = __expf(s[f][3] - nm1);
            rs0 += s[f][0] + s[f][1];
            rs1 += s[f][2] + s[f][3];
        }
        #pragma unroll
        for (int off = 1; off <= 2; off <<= 1) {
            rs0 += __shfl_xor_sync(0xffffffffu, rs0, off);
            rs1 += __shfl_xor_sync(0xffffffffu, rs1, off);
        }
        l0r = l0r*cf0 + rs0;
        l1r = l1r*cf1 + rs1;

        #pragma unroll
        for (int i = 0; i < 10; i++) {
            o[i][0] *= cf0; o[i][1] *= cf0;
            o[i][2] *= cf1; o[i][3] *= cf1;
        }

        #pragma unroll
        for (int kc = 0; kc < 4; kc++) {
            float* f0 = s[kc*2];
            float* f1 = s[kc*2+1];
            unsigned aP [4] = { packh2(f0[0], f0[1]), packh2(f0[2], f0[3]),
                                packh2(f1[0], f1[1]), packh2(f1[2], f1[3]) };
            unsigned aPl[4] = { packl2(f0[0], f0[1]), packl2(f0[2], f0[3]),
                                packl2(f1[0], f1[1]), packl2(f1[2], f1[3]) };
            #pragma unroll
            for (int dt = 0; dt < 5; dt++) {
                unsigned vH[4], vL[4];
                ldsm4t(vH, sVh + ((kc*16 + lrow)*ATSTR + dt*16 + lcol)*2);
                ldsm4t(vL, sVl + ((kc*16 + lrow)*ATSTR + dt*16 + lcol)*2);
                mma16816(o[dt*2],   aP,  &vH[0]);
                mma16816(o[dt*2],   aPl, &vH[0]);
                mma16816(o[dt*2],   aP,  &vL[0]);
                mma16816(o[dt*2+1], aP,  &vH[2]);
                mma16816(o[dt*2+1], aPl, &vH[2]);
                mma16816(o[dt*2+1], aP,  &vL[2]);
            }
        }
        __syncthreads();
    }

    float i0 = 1.f / l0r, i1 = 1.f / l1r;
    int r0 = b*SEQ + q0 + wm + (lane >> 2);
    int r1 = r0 + 8;
    int gc = (lane & 3) * 2;
    #pragma unroll
    for (int nt = 0; nt < 9; nt++) {
        int col = nt*8 + gc;
        size_t off0 = (size_t)r0*HID + h*HD + col;
        size_t off1 = (size_t)r1*HID + h*HD + col;
        float2 p0, p1;
        p0.x = tf32r(o[nt][0]*i0); p0.y = tf32r(o[nt][1]*i0);
        p1.x = tf32r(o[nt][2]*i1); p1.y = tf32r(o[nt][3]*i1);
        *(float2*)(attn + off0) = p0;
        *(float2*)(attn + off1) = p1;
    }
}

// ---------------- launcher ---------------------------------------------------
extern "C" void kernel_launch(void* const* d_in, const int* in_sizes, int n_in,
                              void* d_out, int out_size)
{
    const float* x      = (const float*)d_in[0];
    const float* c      = (const float*)d_in[1];
    const float* cosb   = (const float*)d_in[2];
    const float* sinb   = (const float*)d_in[3];
    const float* w_qkv  = (const float*)d_in[4];
    const float* b_qkv  = (const float*)d_in[5];
    const float* w_proj = (const float*)d_in[6];
    const float* b_proj = (const float*)d_in[7];
    const float* w_mlp1 = (const float*)d_in[8];
    const float* b_mlp1 = (const float*)d_in[9];
    const float* w_mlp2 = (const float*)d_in[10];
    const float* b_mlp2 = (const float*)d_in[11];
    const float* w_ada  = (const float*)d_in[12];
    const float* b_ada  = (const float*)d_in[13];
    float* out = (float*)d_out;

    float *qkv, *res32, *attn32, *h32;
    float *wqkvT, *wprojT, *wm1T, *wm2T;
    bf16 *qkvh, *qkvl;
    cudaGetSymbolAddress((void**)&qkv,    g_qkv);
    cudaGetSymbolAddress((void**)&qkvh,   g_qkvh);
    cudaGetSymbolAddress((void**)&qkvl,   g_qkvl);
    cudaGetSymbolAddress((void**)&res32,  g_res32);
    cudaGetSymbolAddress((void**)&attn32, g_attn32);
    cudaGetSymbolAddress((void**)&h32,    g_h32);
    cudaGetSymbolAddress((void**)&wqkvT,  g_wqkvT);
    cudaGetSymbolAddress((void**)&wprojT, g_wprojT);
    cudaGetSymbolAddress((void**)&wm1T,   g_wm1T);
    cudaGetSymbolAddress((void**)&wm2T,   g_wm2T);

    cudaFuncSetAttribute(k_gemm32, cudaFuncAttributeMaxDynamicSharedMemorySize,
                         GSMEM);
    cudaFuncSetAttribute(k_attn_tc, cudaFuncAttributeMaxDynamicSharedMemorySize,
                         ATT_SMEM);

    // #1: weight transpose + tf32 round -> [N][K]
    k_roundwT<<<TQ4, dim3(32, 8)>>>(w_qkv, w_proj, w_mlp1, w_mlp2);
    // #2: adaLN
    k_ada<<<dim3(6*HID/128, BATCH), 128>>>(c, w_ada, b_ada);
    // #3: LN + modulate (msa)
    k_lnmod<<<TOK, 288>>>(x, res32, 0, HID);
    // #4: qkv GEMM  -- ncu capture slot (256-row tiles)
    k_gemm32<<<dim3(3*HID/128, TOK/256), 512, GSMEM>>>(
        res32, wqkvT, b_qkv, qkv, nullptr,
        TOK, 3*HID, HID, 0, nullptr, 0);
    // #5: fused rope + scale + split
    k_ropesplit<<<(int)((size_t)TOK*3*HID/4/256), 256>>>(cosb, sinb);
    // #6: attention (bf16x3)
    k_attn_tc<<<dim3(SEQ/128, NH, BATCH), 256, ATT_SMEM>>>(qkvh, qkvl, attn32);
    // #7: proj GEMM + gated residual
    k_gemm32<<<dim3(HID/128, TOK/256), 512, GSMEM>>>(
        attn32, wprojT, b_proj, out, nullptr,
        TOK, HID, HID, 1, x, 2*HID);
    // #8: LN + modulate (mlp)
    k_lnmod<<<TOK, 288>>>(out, res32, 3*HID, 4*HID);
    // #9: mlp1 GEMM + gelu
    k_gemm32<<<dim3(4*HID/128, TOK/256), 512, GSMEM>>>(
        res32, wm1T, b_mlp1, nullptr, h32,
        TOK, 4*HID, HID, 2, nullptr, 0);
    // #10: mlp2 GEMM + gated residual
    k_gemm32<<<dim3(HID/128, TOK/256), 512, GSMEM>>>(
        h32, wm2T, b_mlp2, out, nullptr,
        TOK, HID, 4*HID, 1, out, 5*HID);
}

// round 13
// speedup vs baseline: 1.2511x; 1.2511x over previous
#include <cuda_runtime.h>
#include <cuda_bf16.h>
#include <math.h>
#include <stdint.h>

#define HID   1152
#define NH    16
#define HD    72
#define TXT   256
#define BATCH 8
#define SEQ   1280
#define TOK   (BATCH*SEQ)   /* 10240 */
#define EPS   1e-6f

typedef __nv_bfloat16 bf16;

extern __shared__ char dynsmem[];

// ---------------- scratch ----------------------------------------------------
__device__ float g_mod [BATCH*6*HID];
__device__ float g_qkv [TOK*3*HID];
__device__ bf16  g_qkvh[TOK*3*HID], g_qkvl[TOK*3*HID];   // only V-part used
__device__ float g_res32 [TOK*HID];
__device__ float g_attn32[TOK*HID];
__device__ float g_h32   [TOK*4*HID];   // doubles as [TOK][2*HID] q/k buffer pre-mlp1
// tf32-rounded, TRANSPOSED weights: [N][K]
__device__ float g_wqkvT[3*HID*HID];
__device__ float g_wprojT[HID*HID];
__device__ float g_wm1T[4*HID*HID];
__device__ float g_wm2T[HID*4*HID];

// ---------------- helpers ----------------------------------------------------
__device__ __forceinline__ float tf32r(float x) {
    unsigned u; asm("cvt.rna.tf32.f32 %0, %1;" : "=r"(u) : "f"(x));
    return __uint_as_float(u);
}
__device__ __forceinline__ void split1(float x, bf16 &h, bf16 &l) {
    h = __float2bfloat16_rn(x);
    l = __float2bfloat16_rn(x - __bfloat162float(h));
}
__device__ __forceinline__ unsigned packh2(float a, float b) {
    __nv_bfloat16 ha = __float2bfloat16_rn(a), hb = __float2bfloat16_rn(b);
    return (unsigned)__bfloat16_as_ushort(ha) |
           ((unsigned)__bfloat16_as_ushort(hb) << 16);
}
__device__ __forceinline__ unsigned packl2(float a, float b) {
    float ra = a - __bfloat162float(__float2bfloat16_rn(a));
    float rb = b - __bfloat162float(__float2bfloat16_rn(b));
    return packh2(ra, rb);
}
__device__ __forceinline__ unsigned su32(const void* p) {
    return (unsigned)__cvta_generic_to_shared(p);
}
__device__ __forceinline__ void cp16(unsigned dst, const void* src) {
    asm volatile("cp.async.ca.shared.global [%0],[%1],16;\n" :: "r"(dst), "l"(src));
}
__device__ __forceinline__ void cp16cg(unsigned dst, const void* src) {
    asm volatile("cp.async.cg.shared.global [%0],[%1],16;\n" :: "r"(dst), "l"(src));
}
__device__ __forceinline__ void cpcommit() {
    asm volatile("cp.async.commit_group;\n");
}
template<int N_> __device__ __forceinline__ void cpwait() {
    asm volatile("cp.async.wait_group %0;\n" :: "n"(N_));
}
__device__ __forceinline__ void ldsm4(unsigned* r, unsigned a)
{
    asm volatile("ldmatrix.sync.aligned.m8n8.x4.shared.b16 {%0,%1,%2,%3},[%4];\n"
                 : "=r"(r[0]), "=r"(r[1]), "=r"(r[2]), "=r"(r[3]) : "r"(a));
}
__device__ __forceinline__ void ldsm4t(unsigned* r, unsigned a)
{
    asm volatile("ldmatrix.sync.aligned.m8n8.x4.trans.shared.b16 {%0,%1,%2,%3},[%4];\n"
                 : "=r"(r[0]), "=r"(r[1]), "=r"(r[2]), "=r"(r[3]) : "r"(a));
}
__device__ __forceinline__ void mma16816(float* c, const unsigned* a, const unsigned* b)
{
    asm volatile("mma.sync.aligned.m16n8k16.row.col.f32.bf16.bf16.f32 "
                 "{%0,%1,%2,%3},{%4,%5,%6,%7},{%8,%9},{%0,%1,%2,%3};\n"
                 : "+f"(c[0]), "+f"(c[1]), "+f"(c[2]), "+f"(c[3])
                 : "r"(a[0]), "r"(a[1]), "r"(a[2]), "r"(a[3]),
                   "r"(b[0]), "r"(b[1]));
}
__device__ __forceinline__ void mmatf32u(float* c, const unsigned* a, const unsigned* b)
{
    asm volatile("mma.sync.aligned.m16n8k8.row.col.f32.tf32.tf32.f32 "
                 "{%0,%1,%2,%3},{%4,%5,%6,%7},{%8,%9},{%0,%1,%2,%3};\n"
                 : "+f"(c[0]), "+f"(c[1]), "+f"(c[2]), "+f"(c[3])
                 : "r"(a[0]), "r"(a[1]), "r"(a[2]), "r"(a[3]),
                   "r"(b[0]), "r"(b[1]));
}
__device__ __forceinline__ float gelu_tanh(float t) {
    return 0.5f*t*(1.f + tanhf(0.7978845608028654f*(t + 0.044715f*t*t*t)));
}

// ---------------- merged weight transpose + tf32 round -----------------------
#define TQ1 ((3*HID/32)*(HID/32))
#define TQ2 (TQ1 + (HID/32)*(HID/32))
#define TQ3 (TQ2 + (4*HID/32)*(HID/32))
#define TQ4 (TQ3 + (HID/32)*(4*HID/32))
__global__ void k_roundwT(const float* __restrict__ w_qkv,
                          const float* __restrict__ w_proj,
                          const float* __restrict__ w_mlp1,
                          const float* __restrict__ w_mlp2)
{
    __shared__ float tile[32][33];
    int bid = blockIdx.x;
    const float* src; float* dst; int K, N, li;
    if (bid < TQ1)      { src = w_qkv;  dst = g_wqkvT;  K = HID;   N = 3*HID; li = bid; }
    else if (bid < TQ2) { src = w_proj; dst = g_wprojT; K = HID;   N = HID;   li = bid - TQ1; }
    else if (bid < TQ3) { src = w_mlp1; dst = g_wm1T;   K = HID;   N = 4*HID; li = bid - TQ2; }
    else                { src = w_mlp2; dst = g_wm2T;   K = 4*HID; N = HID;   li = bid - TQ3; }
    int ntN = N / 32;
    int nb = (li % ntN) * 32, kb = (li / ntN) * 32;
    int tx = threadIdx.x, ty = threadIdx.y;
    #pragma unroll
    for (int i = 0; i < 4; i++)
        tile[ty + i*8][tx] = src[(size_t)(kb + ty + i*8)*N + nb + tx];
    __syncthreads();
    #pragma unroll
    for (int i = 0; i < 4; i++)
        dst[(size_t)(nb + ty + i*8)*K + kb + tx] = tf32r(tile[tx][ty + i*8]);
}

// ---------------- adaLN ------------------------------------------------------
__global__ void k_ada(const float* __restrict__ c,
                      const float* __restrict__ w,
                      const float* __restrict__ bias)
{
    __shared__ float sc[HID];
    int b = blockIdx.y;
    for (int i = threadIdx.x; i < HID; i += blockDim.x) {
        float v = c[b*HID + i];
        sc[i] = v / (1.f + __expf(-v));
    }
    __syncthreads();
    int n = blockIdx.x*128 + threadIdx.x;
    float acc = bias[n];
    #pragma unroll 4
    for (int k = 0; k < HID; k++) acc += sc[k] * w[(size_t)k*(6*HID) + n];
    g_mod[b*6*HID + n] = acc;
}

// ---------------- fused LN + modulate, writes tf32-rounded fp32 --------------
__global__ void k_lnmod(const float* __restrict__ x, float* __restrict__ o32,
                        int shofs, int scofs)
{
    int row = blockIdx.x;
    int b   = row / SEQ;
    int t   = threadIdx.x;
    float4 v = ((const float4*)(x + (size_t)row*HID))[t];
    float s  = v.x + v.y + v.z + v.w;
    float ss = v.x*v.x + v.y*v.y + v.z*v.z + v.w*v.w;
    #pragma unroll
    for (int off = 16; off >= 1; off >>= 1) {
        s  += __shfl_xor_sync(0xffffffffu, s , off);
        ss += __shfl_xor_sync(0xffffffffu, ss, off);
    }
    __shared__ float rs[9], rss[9];
    __shared__ float smu, srs;
    if ((t & 31) == 0) { rs[t>>5] = s; rss[t>>5] = ss; }
    __syncthreads();
    if (t == 0) {
        float S = 0.f, SS = 0.f;
        #pragma unroll
        for (int i = 0; i < 9; i++) { S += rs[i]; SS += rss[i]; }
        float mu  = S * (1.f/(float)HID);
        float var = SS * (1.f/(float)HID) - mu*mu;
        smu = mu; srs = rsqrtf(var + EPS);
    }
    __syncthreads();
    float mu = smu, r = srs;
    float4 sh = ((const float4*)(g_mod + b*6*HID + shofs))[t];
    float4 sc = ((const float4*)(g_mod + b*6*HID + scofs))[t];
    float4 o;
    o.x = tf32r((1.f+sc.x)*((v.x-mu)*r) + sh.x);
    o.y = tf32r((1.f+sc.y)*((v.y-mu)*r) + sh.y);
    o.z = tf32r((1.f+sc.z)*((v.z-mu)*r) + sh.z);
    o.w = tf32r((1.f+sc.w)*((v.w-mu)*r) + sh.w);
    ((float4*)(o32 + (size_t)row*HID))[t] = o;
}

// ---------------- tf32 GEMM, R11 tile + cross-iter frag prefetch -------------
#define BKF 32
#define APADF 36
#define BPADF 36
#define SMAF (128*APADF)
#define SMBF (128*BPADF)
#define GSMEM (3*(SMAF+SMBF)*4)
__global__ __launch_bounds__(256, 2)
void k_gemm32(const float* __restrict__ A, const float* __restrict__ B,
              const float* __restrict__ bias,
              float* C, float* C2,
              int M, int N, int K, int mode, const float* xres, int gofs)
{
    float* smem = (float*)dynsmem;
    const int t    = threadIdx.x;
    const int lane = t & 31;
    const int wid  = t >> 5;
    const int m0   = blockIdx.y * 128;
    const int n0   = blockIdx.x * 128;
    const int wm   = (wid >> 2) * 64;
    const int wn   = (wid & 3) * 32;
    const int lq   = lane >> 2;
    const int lm   = lane & 3;

    const int a_ro = (lane & 7) + ((lane >> 3) & 1) * 8;
    const int a_co = (lane >> 4) * 4;
    const int b_ro = (lane & 7) + ((lane >> 4) & 1) * 8;
    const int b_co = ((lane >> 3) & 1) * 4;

    float acc[4][4][4];
    #pragma unroll
    for (int i = 0; i < 4; i++)
        #pragma unroll
        for (int j = 0; j < 4; j++)
            #pragma unroll
            for (int q = 0; q < 4; q++) acc[i][j][q] = 0.f;

    const int nIter = K / BKF;

    auto issue = [&](int it, int s) {
        float* as = smem + s*(SMAF + SMBF);
        float* bs = as + SMAF;
        int k0 = it * BKF;
        #pragma unroll
        for (int j = 0; j < 4; j++) {
            int cch = t + j*256;
            int r = cch >> 3, c4 = (cch & 7)*4;
            cp16cg(su32(as + r*APADF + c4), A + (size_t)(m0 + r)*K + k0 + c4);
        }
        #pragma unroll
        for (int j = 0; j < 4; j++) {
            int cch = t + j*256;
            int r = cch >> 3, c4 = (cch & 7)*4;
            cp16cg(su32(bs + r*BPADF + c4), B + (size_t)(n0 + r)*K + k0 + c4);
        }
        cpcommit();
    };

    issue(0, 0);
    issue(1, 1);

    unsigned af[2][4][4], bfr[2][2][4];

    // prologue: stage0 ready -> preload iter0 ks=0 frags into buffer 0
    cpwait<1>();
    __syncthreads();
    {
        float* as = smem;
        float* bs = as + SMAF;
        #pragma unroll
        for (int mt = 0; mt < 4; mt++)
            ldsm4(af[0][mt], su32(as + (wm + mt*16 + a_ro)*APADF + a_co));
        #pragma unroll
        for (int bt = 0; bt < 2; bt++)
            ldsm4(bfr[0][bt], su32(bs + (wn + bt*16 + b_ro)*BPADF + b_co));
    }

    for (int it = 0; it < nIter; it++) {
        cpwait<0>();            // groups <= it+1 complete
        __syncthreads();        // readers of stage (it+2)%3 (iter it-1) done
        if (it + 2 < nIter) issue(it + 2, (it + 2) % 3);

        float* as  = smem + (it % 3)*(SMAF + SMBF);
        float* bs  = as + SMAF;
        float* asN = smem + ((it + 1) % 3)*(SMAF + SMBF);
        float* bsN = asN + SMAF;

        #pragma unroll
        for (int s8 = 0; s8 < 4; s8++) {
            int cur = s8 & 1, nxt = cur ^ 1;
            if (s8 < 3) {
                int ks = (s8 + 1) * 8;
                #pragma unroll
                for (int mt = 0; mt < 4; mt++)
                    ldsm4(af[nxt][mt],
                          su32(as + (wm + mt*16 + a_ro)*APADF + ks + a_co));
                #pragma unroll
                for (int bt = 0; bt < 2; bt++)
                    ldsm4(bfr[nxt][bt],
                          su32(bs + (wn + bt*16 + b_ro)*BPADF + ks + b_co));
            } else if (it + 1 < nIter) {
                // tail: preload NEXT iteration's ks=0 frags (stage (it+1)%3,
                // data guaranteed by cpwait<0> at this iter's top)
                #pragma unroll
                for (int mt = 0; mt < 4; mt++)
                    ldsm4(af[nxt][mt],
                          su32(asN + (wm + mt*16 + a_ro)*APADF + a_co));
                #pragma unroll
                for (int bt = 0; bt < 2; bt++)
                    ldsm4(bfr[nxt][bt],
                          su32(bsN + (wn + bt*16 + b_ro)*BPADF + b_co));
            }
            #pragma unroll
            for (int mt = 0; mt < 4; mt++)
                #pragma unroll
                for (int bt = 0; bt < 2; bt++) {
                    mmatf32u(acc[mt][bt*2],   af[cur][mt], &bfr[cur][bt][0]);
                    mmatf32u(acc[mt][bt*2+1], af[cur][mt], &bfr[cur][bt][2]);
                }
        }
    }

    // epilogue
    #pragma unroll
    for (int mt = 0; mt < 4; mt++) {
        #pragma unroll
        for (int half = 0; half < 2; half++) {
            int row = m0 + wm + mt*16 + lq + half*8;
            int bq  = row / SEQ;
            #pragma unroll
            for (int nt = 0; nt < 4; nt++) {
                int col = n0 + wn + nt*8 + lm*2;
                float2 bb = *(const float2*)(bias + col);
                float v0 = acc[mt][nt][half*2+0] + bb.x;
                float v1 = acc[mt][nt][half*2+1] + bb.y;
                if (mode == 1) {
                    float2 g  = *(const float2*)(g_mod + bq*6*HID + gofs + col);
                    float2 xr = *(const float2*)(xres + (size_t)row*N + col);
                    float2 o; o.x = xr.x + g.x*v0; o.y = xr.y + g.y*v1;
                    *(float2*)(C + (size_t)row*N + col) = o;
                } else if (mode == 2) {
                    float2 o;
                    o.x = tf32r(gelu_tanh(v0));
                    o.y = tf32r(gelu_tanh(v1));
                    *(float2*)(C2 + (size_t)row*N + col) = o;
                } else {
                    float2 o; o.x = v0; o.y = v1;
                    *(float2*)(C + (size_t)row*N + col) = o;
                }
            }
        }
    }
}

// ---------------- fused RoPE + scale + route ---------------------------------
// q,k -> tf32-rounded fp32 into g_h32 viewed as [TOK][2*HID] (q at 0, k at HID)
// v   -> bf16 hi/lo into g_qkvh/g_qkvl (same [TOK][3*HID] offsets as before)
__global__ void k_ropesplit(const float* __restrict__ cosb,
                            const float* __restrict__ sinb)
{
    const float scale = 0.11785113019775793f;
    size_t i = (size_t)blockIdx.x*256 + threadIdx.x;
    size_t e = i*4;
    int row = (int)(e / (3*HID));
    int col = (int)(e % (3*HID));
    int pos = row % SEQ;
    int seg = col / HID;
    int inc = col % HID;            // within-segment column
    int d   = inc % HD;

    float4 v = ((const float4*)g_qkv)[i];
    float o[4] = {v.x, v.y, v.z, v.w};

    if (seg < 2 && pos >= TXT) {
        int p = pos - TXT;
        if (d < 36) {
            float4 v2 = *(const float4*)(g_qkv + e + 36);
            float w2[4] = {v2.x, v2.y, v2.z, v2.w};
            #pragma unroll
            for (int j = 0; j < 4; j++) {
                float cv = cosb[p*36 + d + j], sv = sinb[p*36 + d + j];
                o[j] = o[j]*cv - w2[j]*sv;
            }
        } else {
            float4 v1 = *(const float4*)(g_qkv + e - 36);
            float w1[4] = {v1.x, v1.y, v1.z, v1.w};
            #pragma unroll
            for (int j = 0; j < 4; j++) {
                float cv = cosb[p*36 + d - 36 + j], sv = sinb[p*36 + d - 36 + j];
                o[j] = w1[j]*sv + o[j]*cv;
            }
        }
    }
    if (seg == 0) {
        #pragma unroll
        for (int j = 0; j < 4; j++) o[j] *= scale;
    }
    if (seg < 2) {
        float4 w;
        w.x = tf32r(o[0]); w.y = tf32r(o[1]);
        w.z = tf32r(o[2]); w.w = tf32r(o[3]);
        *(float4*)(g_h32 + (size_t)row*(2*HID) + seg*HID + inc) = w;
    } else {
        bf16 hh[4], ll[4];
        split1(o[0], hh[0], ll[0]); split1(o[1], hh[1], ll[1]);
        split1(o[2], hh[2], ll[2]); split1(o[3], hh[3], ll[3]);
        ((uint2*)g_qkvh)[i] = *(uint2*)hh;
        ((uint2*)g_qkvl)[i] = *(uint2*)ll;
    }
}

// ---------------- flash attention: tf32 QK^T + bf16x3 PV ---------------------
#define QSTR    76                         /* fp32 elems per Q/K row */
#define QF_B    (128*QSTR*4)               /* 38912 */
#define KF_B    (64*QSTR*4)                /* 19456 */
#define VT_B    (64*88*2)                  /* 11264 */
#define ATT_SMEM (QF_B + 2*KF_B + 4*VT_B) /* 122880 */
__global__ __launch_bounds__(256)
void k_attn_tc(const float* __restrict__ qk,
               const bf16* __restrict__ vh, const bf16* __restrict__ vl,
               float* __restrict__ attn)
{
    char* smem = dynsmem;
    const unsigned sb    = su32(smem);
    const unsigned sQ    = sb;
    const unsigned KBASE = sb + QF_B;
    const unsigned VBASE = sb + QF_B + 2*KF_B;

    const int t    = threadIdx.x;
    const int lane = t & 31;
    const int wid  = t >> 5;
    const int q0   = blockIdx.x * 128;
    const int h    = blockIdx.y;
    const int b    = blockIdx.z;
    const int wm   = wid * 16;
    const int lrow = lane & 15;
    const int lcol = (lane >> 4) * 8;

    // GEMM-style tf32 ldmatrix lane offsets
    const int a_ro = (lane & 7) + ((lane >> 3) & 1) * 8;
    const int a_co = (lane >> 4) * 4;
    const int b_ro = (lane & 7) + ((lane >> 4) & 1) * 8;
    const int b_co = ((lane >> 3) & 1) * 4;

    // zero smem (V pads feed discarded o[9]; keep clean anyway)
    #pragma unroll
    for (int i = 0; i < ATT_SMEM/16/256; i++) {
        uint4 z = {0,0,0,0};
        *(uint4*)(smem + (i*256 + t)*16) = z;
    }
    __syncthreads();

    // stage Q: 128 rows x 18 cp16 (fp32) = 2304
    {
        #pragma unroll
        for (int rep = 0; rep < 9; rep++) {
            int id  = rep*256 + t;
            int row = id / 18, c = id % 18;
            const float* src = qk + (size_t)(b*SEQ + q0 + row)*(2*HID) + h*HD + c*4;
            cp16(sQ + row*(QSTR*4) + c*16, src);
        }
        cpcommit();
    }

    auto stage_kv = [&](int kt, int s) {
        unsigned sK  = KBASE + s*KF_B;
        unsigned sVh = VBASE + s*2*VT_B;
        unsigned sVl = sVh + VT_B;
        #pragma unroll
        for (int rep = 0; rep < 9; rep++) {
            int id = rep*256 + t;            // 0..2303
            if (id < 1152) {                 // K fp32: 64 rows x 18
                int row = id / 18, c = id % 18;
                const float* src = qk + (size_t)(b*SEQ + kt*64 + row)*(2*HID)
                                 + HID + h*HD + c*4;
                cp16(sK + row*(QSTR*4) + c*16, src);
            } else {                          // V bf16 hi/lo: 2 x 64 x 9
                int id2 = id - 1152;
                int op  = id2 / 576;
                int rid = id2 % 576;
                int row = rid / 9, c8 = rid % 9;
                const bf16* src = (op ? vl : vh)
                    + (size_t)(b*SEQ + kt*64 + row)*(3*HID) + 2*HID + h*HD + c8*8;
                cp16((op ? sVl : sVh) + (row*88 + c8*8)*2, src);
            }
        }
        cpcommit();
    };

    stage_kv(0, 0);

    float m0r = -3.0e38f, m1r = -3.0e38f, l0r = 0.f, l1r = 0.f;
    float o[10][4];
    #pragma unroll
    for (int i = 0; i < 10; i++)
        #pragma unroll
        for (int j = 0; j < 4; j++) o[i][j] = 0.f;

    const int NKV = SEQ/64;
    for (int kt = 0; kt < NKV; kt++) {
        cpwait<0>();
        __syncthreads();
        if (kt + 1 < NKV) stage_kv(kt + 1, (kt + 1) & 1);

        unsigned sK  = KBASE + (kt & 1)*KF_B;
        unsigned sVh = VBASE + (kt & 1)*2*VT_B;
        unsigned sVl = sVh + VT_B;

        // ---- S = Q K^T in tf32 (k = 72 = 9 x k8, no padding in k) ----
        float s[8][4];
        #pragma unroll
        for (int i = 0; i < 8; i++)
            #pragma unroll
            for (int j = 0; j < 4; j++) s[i][j] = 0.f;

        #pragma unroll
        for (int kc = 0; kc < 9; kc++) {
            unsigned aQ[4];
            ldsm4(aQ, sQ + ((wm + a_ro)*QSTR + kc*8 + a_co)*4);
            #pragma unroll
            for (int jt = 0; jt < 4; jt++) {
                unsigned bK[4];
                ldsm4(bK, sK + ((jt*16 + b_ro)*QSTR + kc*8 + b_co)*4);
                mmatf32u(s[jt*2],   aQ, &bK[0]);
                mmatf32u(s[jt*2+1], aQ, &bK[2]);
            }
        }

        // ---- online softmax (rows lq and lq+8 per warp) ----
        float tm0 = -3.0e38f, tm1 = -3.0e38f;
        #pragma unroll
        for (int f = 0; f < 8; f++) {
            tm0 = fmaxf(tm0, fmaxf(s[f][0], s[f][1]));
            tm1 = fmaxf(tm1, fmaxf(s[f][2], s[f][3]));
        }
        #pragma unroll
        for (int off = 1; off <= 2; off <<= 1) {
            tm0 = fmaxf(tm0, __shfl_xor_sync(0xffffffffu, tm0, off));
            tm1 = fmaxf(tm1, __shfl_xor_sync(0xffffffffu, tm1, off));
        }
        float nm0 = fmaxf(m0r, tm0), nm1 = fmaxf(m1r, tm1);
        float cf0 = __expf(m0r - nm0), cf1 = __expf(m1r - nm1);
        m0r = nm0; m1r = nm1;

        float rs0 = 0.f, rs1 = 0.f;
        #pragma unroll
        for (int f = 0; f < 8; f++) {
            s[f][0] = __expf(s[f][0] - nm0);
            s[f][1] = __expf(s[f][1] - nm0);
            s[f][2] = __expf(s[f][2] - nm1);
            s[f][3] = __expf(s[f][3] - nm1);
            rs0 += s[f][0] + s[f][1];
            rs1 += s[f][2] + s[f][3];
        }
        #pragma unroll
        for (int off = 1; off <= 2; off <<= 1) {
            rs0 += __shfl_xor_sync(0xffffffffu, rs0, off);
            rs1 += __shfl_xor_sync(0xffffffffu, rs1, off);
        }
        l0r = l0r*cf0 + rs0;
        l1r = l1r*cf1 + rs1;

        #pragma unroll
        for (int i = 0; i < 10; i++) {
            o[i][0] *= cf0; o[i][1] *= cf0;
            o[i][2] *= cf1; o[i][3] *= cf1;
        }

        // ---- O += P V (bf16x3, unchanged) ----
        #pragma unroll
        for (int kc = 0; kc < 4; kc++) {
            float* f0 = s[kc*2];
            float* f1 = s[kc*2+1];
            unsigned aP [4] = { packh2(f0[0], f0[1]), packh2(f0[2], f0[3]),
                                packh2(f1[0], f1[1]), packh2(f1[2], f1[3]) };
            unsigned aPl[4] = { packl2(f0[0], f0[1]), packl2(f0[2], f0[3]),
                                packl2(f1[0], f1[1]), packl2(f1[2], f1[3]) };
            #pragma unroll
            for (int dt = 0; dt < 5; dt++) {
                unsigned vH[4], vL[4];
                ldsm4t(vH, sVh + ((kc*16 + lrow)*88 + dt*16 + lcol)*2);
                ldsm4t(vL, sVl + ((kc*16 + lrow)*88 + dt*16 + lcol)*2);
                mma16816(o[dt*2],   aP,  &vH[0]);
                mma16816(o[dt*2],   aPl, &vH[0]);
                mma16816(o[dt*2],   aP,  &vL[0]);
                mma16816(o[dt*2+1], aP,  &vH[2]);
                mma16816(o[dt*2+1], aPl, &vH[2]);
                mma16816(o[dt*2+1], aP,  &vL[2]);
            }
        }
        __syncthreads();
    }

    float i0 = 1.f / l0r, i1 = 1.f / l1r;
    int r0 = b*SEQ + q0 + wm + (lane >> 2);
    int r1 = r0 + 8;
    int gc = (lane & 3) * 2;
    #pragma unroll
    for (int nt = 0; nt < 9; nt++) {
        int col = nt*8 + gc;
        size_t off0 = (size_t)r0*HID + h*HD + col;
        size_t off1 = (size_t)r1*HID + h*HD + col;
        float2 p0, p1;
        p0.x = tf32r(o[nt][0]*i0); p0.y = tf32r(o[nt][1]*i0);
        p1.x = tf32r(o[nt][2]*i1); p1.y = tf32r(o[nt][3]*i1);
        *(float2*)(attn + off0) = p0;
        *(float2*)(attn + off1) = p1;
    }
}

// ---------------- launcher ---------------------------------------------------
extern "C" void kernel_launch(void* const* d_in, const int* in_sizes, int n_in,
                              void* d_out, int out_size)
{
    const float* x      = (const float*)d_in[0];
    const float* c      = (const float*)d_in[1];
    const float* cosb   = (const float*)d_in[2];
    const float* sinb   = (const float*)d_in[3];
    const float* w_qkv  = (const float*)d_in[4];
    const float* b_qkv  = (const float*)d_in[5];
    const float* w_proj = (const float*)d_in[6];
    const float* b_proj = (const float*)d_in[7];
    const float* w_mlp1 = (const float*)d_in[8];
    const float* b_mlp1 = (const float*)d_in[9];
    const float* w_mlp2 = (const float*)d_in[10];
    const float* b_mlp2 = (const float*)d_in[11];
    const float* w_ada  = (const float*)d_in[12];
    const float* b_ada  = (const float*)d_in[13];
    float* out = (float*)d_out;

    float *qkv, *res32, *attn32, *h32;
    float *wqkvT, *wprojT, *wm1T, *wm2T;
    bf16 *qkvh, *qkvl;
    cudaGetSymbolAddress((void**)&qkv,    g_qkv);
    cudaGetSymbolAddress((void**)&qkvh,   g_qkvh);
    cudaGetSymbolAddress((void**)&qkvl,   g_qkvl);
    cudaGetSymbolAddress((void**)&res32,  g_res32);
    cudaGetSymbolAddress((void**)&attn32, g_attn32);
    cudaGetSymbolAddress((void**)&h32,    g_h32);
    cudaGetSymbolAddress((void**)&wqkvT,  g_wqkvT);
    cudaGetSymbolAddress((void**)&wprojT, g_wprojT);
    cudaGetSymbolAddress((void**)&wm1T,   g_wm1T);
    cudaGetSymbolAddress((void**)&wm2T,   g_wm2T);

    cudaFuncSetAttribute(k_gemm32, cudaFuncAttributeMaxDynamicSharedMemorySize,
                         GSMEM);
    cudaFuncSetAttribute(k_attn_tc, cudaFuncAttributeMaxDynamicSharedMemorySize,
                         ATT_SMEM);

    // #1: weight transpose + tf32 round -> [N][K]
    k_roundwT<<<TQ4, dim3(32, 8)>>>(w_qkv, w_proj, w_mlp1, w_mlp2);
    // #2: adaLN
    k_ada<<<dim3(6*HID/128, BATCH), 128>>>(c, w_ada, b_ada);
    // #3: LN + modulate (msa)
    k_lnmod<<<TOK, 288>>>(x, res32, 0, HID);
    // #4: qkv GEMM  -- ncu capture slot
    k_gemm32<<<dim3(3*HID/128, TOK/128), 256, GSMEM>>>(
        res32, wqkvT, b_qkv, qkv, nullptr,
        TOK, 3*HID, HID, 0, nullptr, 0);
    // #5: fused rope + scale + route (q/k fp32 -> g_h32, v bf16 hi/lo)
    k_ropesplit<<<(int)((size_t)TOK*3*HID/4/256), 256>>>(cosb, sinb);
    // #6: attention (tf32 QK + bf16x3 PV)
    k_attn_tc<<<dim3(SEQ/128, NH, BATCH), 256, ATT_SMEM>>>(h32, qkvh, qkvl,
                                                           attn32);
    // #7: proj GEMM + gated residual
    k_gemm32<<<dim3(HID/128, TOK/128), 256, GSMEM>>>(
        attn32, wprojT, b_proj, out, nullptr,
        TOK, HID, HID, 1, x, 2*HID);
    // #8: LN + modulate (mlp)
    k_lnmod<<<TOK, 288>>>(out, res32, 3*HID, 4*HID);
    // #9: mlp1 GEMM + gelu (overwrites g_h32 -- q/k no longer needed)
    k_gemm32<<<dim3(4*HID/128, TOK/128), 256, GSMEM>>>(
        res32, wm1T, b_mlp1, nullptr, h32,
        TOK, 4*HID, HID, 2, nullptr, 0);
    // #10: mlp2 GEMM + gated residual
    k_gemm32<<<dim3(HID/128, TOK/128), 256, GSMEM>>>(
        h32, wm2T, b_mlp2, out, nullptr,
        TOK, HID, 4*HID, 1, out, 5*HID);
}

// round 15
// speedup vs baseline: 1.2736x; 1.0180x over previous
#include <cuda_runtime.h>
#include <cuda_bf16.h>
#include <math.h>
#include <stdint.h>

#define HID   1152
#define NH    16
#define HD    72
#define TXT   256
#define BATCH 8
#define SEQ   1280
#define TOK   (BATCH*SEQ)   /* 10240 */
#define EPS   1e-6f

typedef __nv_bfloat16 bf16;

extern __shared__ char dynsmem[];

// ---------------- scratch ----------------------------------------------------
__device__ float g_mod [BATCH*6*HID];
__device__ float g_qkv [TOK*3*HID];
__device__ bf16  g_qkvh[TOK*3*HID], g_qkvl[TOK*3*HID];   // only V-part used
__device__ float g_res32 [TOK*HID];
__device__ float g_attn32[TOK*HID];
__device__ float g_h32   [TOK*4*HID];   // doubles as [TOK][2*HID] q/k buffer pre-mlp1
// tf32-rounded, TRANSPOSED weights: [N][K]
__device__ float g_wqkvT[3*HID*HID];
__device__ float g_wprojT[HID*HID];
__device__ float g_wm1T[4*HID*HID];
__device__ float g_wm2T[HID*4*HID];

// ---------------- helpers ----------------------------------------------------
__device__ __forceinline__ float tf32r(float x) {
    unsigned u; asm("cvt.rna.tf32.f32 %0, %1;" : "=r"(u) : "f"(x));
    return __uint_as_float(u);
}
__device__ __forceinline__ void split1(float x, bf16 &h, bf16 &l) {
    h = __float2bfloat16_rn(x);
    l = __float2bfloat16_rn(x - __bfloat162float(h));
}
__device__ __forceinline__ unsigned packh2(float a, float b) {
    __nv_bfloat16 ha = __float2bfloat16_rn(a), hb = __float2bfloat16_rn(b);
    return (unsigned)__bfloat16_as_ushort(ha) |
           ((unsigned)__bfloat16_as_ushort(hb) << 16);
}
__device__ __forceinline__ unsigned packl2(float a, float b) {
    float ra = a - __bfloat162float(__float2bfloat16_rn(a));
    float rb = b - __bfloat162float(__float2bfloat16_rn(b));
    return packh2(ra, rb);
}
__device__ __forceinline__ unsigned su32(const void* p) {
    return (unsigned)__cvta_generic_to_shared(p);
}
__device__ __forceinline__ void cp16(unsigned dst, const void* src) {
    asm volatile("cp.async.ca.shared.global [%0],[%1],16;\n" :: "r"(dst), "l"(src));
}
__device__ __forceinline__ void cp16cg(unsigned dst, const void* src) {
    asm volatile("cp.async.cg.shared.global [%0],[%1],16;\n" :: "r"(dst), "l"(src));
}
__device__ __forceinline__ void cpcommit() {
    asm volatile("cp.async.commit_group;\n");
}
template<int N_> __device__ __forceinline__ void cpwait() {
    asm volatile("cp.async.wait_group %0;\n" :: "n"(N_));
}
__device__ __forceinline__ void ldsm4(unsigned* r, unsigned a)
{
    asm volatile("ldmatrix.sync.aligned.m8n8.x4.shared.b16 {%0,%1,%2,%3},[%4];\n"
                 : "=r"(r[0]), "=r"(r[1]), "=r"(r[2]), "=r"(r[3]) : "r"(a));
}
__device__ __forceinline__ void ldsm4t(unsigned* r, unsigned a)
{
    asm volatile("ldmatrix.sync.aligned.m8n8.x4.trans.shared.b16 {%0,%1,%2,%3},[%4];\n"
                 : "=r"(r[0]), "=r"(r[1]), "=r"(r[2]), "=r"(r[3]) : "r"(a));
}
__device__ __forceinline__ void mma16816(float* c, const unsigned* a, const unsigned* b)
{
    asm volatile("mma.sync.aligned.m16n8k16.row.col.f32.bf16.bf16.f32 "
                 "{%0,%1,%2,%3},{%4,%5,%6,%7},{%8,%9},{%0,%1,%2,%3};\n"
                 : "+f"(c[0]), "+f"(c[1]), "+f"(c[2]), "+f"(c[3])
                 : "r"(a[0]), "r"(a[1]), "r"(a[2]), "r"(a[3]),
                   "r"(b[0]), "r"(b[1]));
}
__device__ __forceinline__ void mmatf32u(float* c, const unsigned* a, const unsigned* b)
{
    asm volatile("mma.sync.aligned.m16n8k8.row.col.f32.tf32.tf32.f32 "
                 "{%0,%1,%2,%3},{%4,%5,%6,%7},{%8,%9},{%0,%1,%2,%3};\n"
                 : "+f"(c[0]), "+f"(c[1]), "+f"(c[2]), "+f"(c[3])
                 : "r"(a[0]), "r"(a[1]), "r"(a[2]), "r"(a[3]),
                   "r"(b[0]), "r"(b[1]));
}
__device__ __forceinline__ float gelu_tanh(float t) {
    return 0.5f*t*(1.f + tanhf(0.7978845608028654f*(t + 0.044715f*t*t*t)));
}

// ---------------- merged weight transpose + tf32 round -----------------------
#define TQ1 ((3*HID/32)*(HID/32))
#define TQ2 (TQ1 + (HID/32)*(HID/32))
#define TQ3 (TQ2 + (4*HID/32)*(HID/32))
#define TQ4 (TQ3 + (HID/32)*(4*HID/32))
__global__ void k_roundwT(const float* __restrict__ w_qkv,
                          const float* __restrict__ w_proj,
                          const float* __restrict__ w_mlp1,
                          const float* __restrict__ w_mlp2)
{
    __shared__ float tile[32][33];
    int bid = blockIdx.x;
    const float* src; float* dst; int K, N, li;
    if (bid < TQ1)      { src = w_qkv;  dst = g_wqkvT;  K = HID;   N = 3*HID; li = bid; }
    else if (bid < TQ2) { src = w_proj; dst = g_wprojT; K = HID;   N = HID;   li = bid - TQ1; }
    else if (bid < TQ3) { src = w_mlp1; dst = g_wm1T;   K = HID;   N = 4*HID; li = bid - TQ2; }
    else                { src = w_mlp2; dst = g_wm2T;   K = 4*HID; N = HID;   li = bid - TQ3; }
    int ntN = N / 32;
    int nb = (li % ntN) * 32, kb = (li / ntN) * 32;
    int tx = threadIdx.x, ty = threadIdx.y;
    #pragma unroll
    for (int i = 0; i < 4; i++)
        tile[ty + i*8][tx] = src[(size_t)(kb + ty + i*8)*N + nb + tx];
    __syncthreads();
    #pragma unroll
    for (int i = 0; i < 4; i++)
        dst[(size_t)(nb + ty + i*8)*K + kb + tx] = tf32r(tile[tx][ty + i*8]);
}

// ---------------- adaLN ------------------------------------------------------
__global__ void k_ada(const float* __restrict__ c,
                      const float* __restrict__ w,
                      const float* __restrict__ bias)
{
    __shared__ float sc[HID];
    int b = blockIdx.y;
    for (int i = threadIdx.x; i < HID; i += blockDim.x) {
        float v = c[b*HID + i];
        sc[i] = v / (1.f + __expf(-v));
    }
    __syncthreads();
    int n = blockIdx.x*128 + threadIdx.x;
    float acc = bias[n];
    #pragma unroll 4
    for (int k = 0; k < HID; k++) acc += sc[k] * w[(size_t)k*(6*HID) + n];
    g_mod[b*6*HID + n] = acc;
}

// ---------------- fused LN + modulate, writes tf32-rounded fp32 --------------
__global__ void k_lnmod(const float* __restrict__ x, float* __restrict__ o32,
                        int shofs, int scofs)
{
    int row = blockIdx.x;
    int b   = row / SEQ;
    int t   = threadIdx.x;
    float4 v = ((const float4*)(x + (size_t)row*HID))[t];
    float s  = v.x + v.y + v.z + v.w;
    float ss = v.x*v.x + v.y*v.y + v.z*v.z + v.w*v.w;
    #pragma unroll
    for (int off = 16; off >= 1; off >>= 1) {
        s  += __shfl_xor_sync(0xffffffffu, s , off);
        ss += __shfl_xor_sync(0xffffffffu, ss, off);
    }
    __shared__ float rs[9], rss[9];
    __shared__ float smu, srs;
    if ((t & 31) == 0) { rs[t>>5] = s; rss[t>>5] = ss; }
    __syncthreads();
    if (t == 0) {
        float S = 0.f, SS = 0.f;
        #pragma unroll
        for (int i = 0; i < 9; i++) { S += rs[i]; SS += rss[i]; }
        float mu  = S * (1.f/(float)HID);
        float var = SS * (1.f/(float)HID) - mu*mu;
        smu = mu; srs = rsqrtf(var + EPS);
    }
    __syncthreads();
    float mu = smu, r = srs;
    float4 sh = ((const float4*)(g_mod + b*6*HID + shofs))[t];
    float4 sc = ((const float4*)(g_mod + b*6*HID + scofs))[t];
    float4 o;
    o.x = tf32r((1.f+sc.x)*((v.x-mu)*r) + sh.x);
    o.y = tf32r((1.f+sc.y)*((v.y-mu)*r) + sh.y);
    o.z = tf32r((1.f+sc.z)*((v.z-mu)*r) + sh.z);
    o.w = tf32r((1.f+sc.w)*((v.w-mu)*r) + sh.w);
    ((float4*)(o32 + (size_t)row*HID))[t] = o;
}

// ---------------- tf32 GEMM: deferred cpwait with correct barrier ------------
// per iter: issue(it+2) | s8=0..2 on stage it | cpwait | sync | tail prefetch
#define BKF 32
#define APADF 36
#define BPADF 36
#define SMAF (128*APADF)
#define SMBF (128*BPADF)
#define GSMEM (3*(SMAF+SMBF)*4)
__global__ __launch_bounds__(256, 2)
void k_gemm32(const float* __restrict__ A, const float* __restrict__ B,
              const float* __restrict__ bias,
              float* C, float* C2,
              int M, int N, int K, int mode, const float* xres, int gofs)
{
    float* smem = (float*)dynsmem;
    const int t    = threadIdx.x;
    const int lane = t & 31;
    const int wid  = t >> 5;
    const int m0   = blockIdx.y * 128;
    const int n0   = blockIdx.x * 128;
    const int wm   = (wid >> 2) * 64;
    const int wn   = (wid & 3) * 32;
    const int lq   = lane >> 2;
    const int lm   = lane & 3;

    const int a_ro = (lane & 7) + ((lane >> 3) & 1) * 8;
    const int a_co = (lane >> 4) * 4;
    const int b_ro = (lane & 7) + ((lane >> 4) & 1) * 8;
    const int b_co = ((lane >> 3) & 1) * 4;

    float acc[4][4][4];
    #pragma unroll
    for (int i = 0; i < 4; i++)
        #pragma unroll
        for (int j = 0; j < 4; j++)
            #pragma unroll
            for (int q = 0; q < 4; q++) acc[i][j][q] = 0.f;

    const int nIter = K / BKF;

    auto issue = [&](int it, int s) {
        float* as = smem + s*(SMAF + SMBF);
        float* bs = as + SMAF;
        int k0 = it * BKF;
        #pragma unroll
        for (int j = 0; j < 4; j++) {
            int cch = t + j*256;
            int r = cch >> 3, c4 = (cch & 7)*4;
            cp16cg(su32(as + r*APADF + c4), A + (size_t)(m0 + r)*K + k0 + c4);
        }
        #pragma unroll
        for (int j = 0; j < 4; j++) {
            int cch = t + j*256;
            int r = cch >> 3, c4 = (cch & 7)*4;
            cp16cg(su32(bs + r*BPADF + c4), B + (size_t)(n0 + r)*K + k0 + c4);
        }
        cpcommit();
    };

    issue(0, 0);
    issue(1, 1);

    unsigned af[2][4][4], bfr[2][2][4];

    // prologue: group 0 complete + barrier -> preload iter0 ks=0 frags
    cpwait<1>();
    __syncthreads();
    {
        float* as = smem;
        float* bs = as + SMAF;
        #pragma unroll
        for (int mt = 0; mt < 4; mt++)
            ldsm4(af[0][mt], su32(as + (wm + mt*16 + a_ro)*APADF + a_co));
        #pragma unroll
        for (int bt = 0; bt < 2; bt++)
            ldsm4(bfr[0][bt], su32(bs + (wn + bt*16 + b_ro)*BPADF + b_co));
    }

    for (int it = 0; it < nIter; it++) {
        // stage (it+2)%3's readers all finished before iter it-1's barrier
        if (it + 2 < nIter) issue(it + 2, (it + 2) % 3);

        float* as  = smem + (it % 3)*(SMAF + SMBF);
        float* bs  = as + SMAF;
        float* asN = smem + ((it + 1) % 3)*(SMAF + SMBF);
        float* bsN = asN + SMAF;

        // s8 = 0..2: stage it (complete+visible since iter it-1's wait+barrier)
        #pragma unroll
        for (int s8 = 0; s8 < 3; s8++) {
            int cur = s8 & 1, nxt = cur ^ 1;
            int ks = (s8 + 1) * 8;
            #pragma unroll
            for (int mt = 0; mt < 4; mt++)
                ldsm4(af[nxt][mt],
                      su32(as + (wm + mt*16 + a_ro)*APADF + ks + a_co));
            #pragma unroll
            for (int bt = 0; bt < 2; bt++)
                ldsm4(bfr[nxt][bt],
                      su32(bs + (wn + bt*16 + b_ro)*BPADF + ks + b_co));
            #pragma unroll
            for (int mt = 0; mt < 4; mt++)
                #pragma unroll
                for (int bt = 0; bt < 2; bt++) {
                    mmatf32u(acc[mt][bt*2],   af[cur][mt], &bfr[cur][bt][0]);
                    mmatf32u(acc[mt][bt*2+1], af[cur][mt], &bfr[cur][bt][2]);
                }
        }

        // wait for group it+1 (own copies), then barrier for cross-thread
        // visibility BEFORE the tail reads stage it+1  (R14's missing step)
        if (it + 2 < nIter) cpwait<1>(); else cpwait<0>();
        __syncthreads();

        // s8 = 3: MMA on buffer 1 (ks=24) + prefetch next iter's ks=0 frags
        {
            if (it + 1 < nIter) {
                #pragma unroll
                for (int mt = 0; mt < 4; mt++)
                    ldsm4(af[0][mt],
                          su32(asN + (wm + mt*16 + a_ro)*APADF + a_co));
                #pragma unroll
                for (int bt = 0; bt < 2; bt++)
                    ldsm4(bfr[0][bt],
                          su32(bsN + (wn + bt*16 + b_ro)*BPADF + b_co));
            }
            #pragma unroll
            for (int mt = 0; mt < 4; mt++)
                #pragma unroll
                for (int bt = 0; bt < 2; bt++) {
                    mmatf32u(acc[mt][bt*2],   af[1][mt], &bfr[1][bt][0]);
                    mmatf32u(acc[mt][bt*2+1], af[1][mt], &bfr[1][bt][2]);
                }
        }
    }

    // epilogue
    #pragma unroll
    for (int mt = 0; mt < 4; mt++) {
        #pragma unroll
        for (int half = 0; half < 2; half++) {
            int row = m0 + wm + mt*16 + lq + half*8;
            int bq  = row / SEQ;
            #pragma unroll
            for (int nt = 0; nt < 4; nt++) {
                int col = n0 + wn + nt*8 + lm*2;
                float2 bb = *(const float2*)(bias + col);
                float v0 = acc[mt][nt][half*2+0] + bb.x;
                float v1 = acc[mt][nt][half*2+1] + bb.y;
                if (mode == 1) {
                    float2 g  = *(const float2*)(g_mod + bq*6*HID + gofs + col);
                    float2 xr = *(const float2*)(xres + (size_t)row*N + col);
                    float2 o; o.x = xr.x + g.x*v0; o.y = xr.y + g.y*v1;
                    *(float2*)(C + (size_t)row*N + col) = o;
                } else if (mode == 2) {
                    float2 o;
                    o.x = tf32r(gelu_tanh(v0));
                    o.y = tf32r(gelu_tanh(v1));
                    *(float2*)(C2 + (size_t)row*N + col) = o;
                } else {
                    float2 o; o.x = v0; o.y = v1;
                    *(float2*)(C + (size_t)row*N + col) = o;
                }
            }
        }
    }
}

// ---------------- fused RoPE + scale + route ---------------------------------
__global__ void k_ropesplit(const float* __restrict__ cosb,
                            const float* __restrict__ sinb)
{
    const float scale = 0.11785113019775793f;
    size_t i = (size_t)blockIdx.x*256 + threadIdx.x;
    size_t e = i*4;
    int row = (int)(e / (3*HID));
    int col = (int)(e % (3*HID));
    int pos = row % SEQ;
    int seg = col / HID;
    int inc = col % HID;
    int d   = inc % HD;

    float4 v = ((const float4*)g_qkv)[i];
    float o[4] = {v.x, v.y, v.z, v.w};

    if (seg < 2 && pos >= TXT) {
        int p = pos - TXT;
        if (d < 36) {
            float4 v2 = *(const float4*)(g_qkv + e + 36);
            float w2[4] = {v2.x, v2.y, v2.z, v2.w};
            #pragma unroll
            for (int j = 0; j < 4; j++) {
                float cv = cosb[p*36 + d + j], sv = sinb[p*36 + d + j];
                o[j] = o[j]*cv - w2[j]*sv;
            }
        } else {
            float4 v1 = *(const float4*)(g_qkv + e - 36);
            float w1[4] = {v1.x, v1.y, v1.z, v1.w};
            #pragma unroll
            for (int j = 0; j < 4; j++) {
                float cv = cosb[p*36 + d - 36 + j], sv = sinb[p*36 + d - 36 + j];
                o[j] = w1[j]*sv + o[j]*cv;
            }
        }
    }
    if (seg == 0) {
        #pragma unroll
        for (int j = 0; j < 4; j++) o[j] *= scale;
    }
    if (seg < 2) {
        float4 w;
        w.x = tf32r(o[0]); w.y = tf32r(o[1]);
        w.z = tf32r(o[2]); w.w = tf32r(o[3]);
        *(float4*)(g_h32 + (size_t)row*(2*HID) + seg*HID + inc) = w;
    } else {
        bf16 hh[4], ll[4];
        split1(o[0], hh[0], ll[0]); split1(o[1], hh[1], ll[1]);
        split1(o[2], hh[2], ll[2]); split1(o[3], hh[3], ll[3]);
        ((uint2*)g_qkvh)[i] = *(uint2*)hh;
        ((uint2*)g_qkvl)[i] = *(uint2*)ll;
    }
}

// ---------------- flash attention: tf32 QK^T + bf16x3 PV (R13, passing) ------
#define QSTR    76
#define QF_B    (128*QSTR*4)
#define KF_B    (64*QSTR*4)
#define VT_B    (64*88*2)
#define ATT_SMEM (QF_B + 2*KF_B + 4*VT_B)
__global__ __launch_bounds__(256)
void k_attn_tc(const float* __restrict__ qk,
               const bf16* __restrict__ vh, const bf16* __restrict__ vl,
               float* __restrict__ attn)
{
    char* smem = dynsmem;
    const unsigned sb    = su32(smem);
    const unsigned sQ    = sb;
    const unsigned KBASE = sb + QF_B;
    const unsigned VBASE = sb + QF_B + 2*KF_B;

    const int t    = threadIdx.x;
    const int lane = t & 31;
    const int wid  = t >> 5;
    const int q0   = blockIdx.x * 128;
    const int h    = blockIdx.y;
    const int b    = blockIdx.z;
    const int wm   = wid * 16;
    const int lrow = lane & 15;
    const int lcol = (lane >> 4) * 8;

    const int a_ro = (lane & 7) + ((lane >> 3) & 1) * 8;
    const int a_co = (lane >> 4) * 4;
    const int b_ro = (lane & 7) + ((lane >> 4) & 1) * 8;
    const int b_co = ((lane >> 3) & 1) * 4;

    #pragma unroll
    for (int i = 0; i < ATT_SMEM/16/256; i++) {
        uint4 z = {0,0,0,0};
        *(uint4*)(smem + (i*256 + t)*16) = z;
    }
    __syncthreads();

    {
        #pragma unroll
        for (int rep = 0; rep < 9; rep++) {
            int id  = rep*256 + t;
            int row = id / 18, c = id % 18;
            const float* src = qk + (size_t)(b*SEQ + q0 + row)*(2*HID) + h*HD + c*4;
            cp16(sQ + row*(QSTR*4) + c*16, src);
        }
        cpcommit();
    }

    auto stage_kv = [&](int kt, int s) {
        unsigned sK  = KBASE + s*KF_B;
        unsigned sVh = VBASE + s*2*VT_B;
        unsigned sVl = sVh + VT_B;
        #pragma unroll
        for (int rep = 0; rep < 9; rep++) {
            int id = rep*256 + t;
            if (id < 1152) {
                int row = id / 18, c = id % 18;
                const float* src = qk + (size_t)(b*SEQ + kt*64 + row)*(2*HID)
                                 + HID + h*HD + c*4;
                cp16(sK + row*(QSTR*4) + c*16, src);
            } else {
                int id2 = id - 1152;
                int op  = id2 / 576;
                int rid = id2 % 576;
                int row = rid / 9, c8 = rid % 9;
                const bf16* src = (op ? vl : vh)
                    + (size_t)(b*SEQ + kt*64 + row)*(3*HID) + 2*HID + h*HD + c8*8;
                cp16((op ? sVl : sVh) + (row*88 + c8*8)*2, src);
            }
        }
        cpcommit();
    };

    stage_kv(0, 0);

    float m0r = -3.0e38f, m1r = -3.0e38f, l0r = 0.f, l1r = 0.f;
    float o[10][4];
    #pragma unroll
    for (int i = 0; i < 10; i++)
        #pragma unroll
        for (int j = 0; j < 4; j++) o[i][j] = 0.f;

    const int NKV = SEQ/64;
    for (int kt = 0; kt < NKV; kt++) {
        cpwait<0>();
        __syncthreads();
        if (kt + 1 < NKV) stage_kv(kt + 1, (kt + 1) & 1);

        unsigned sK  = KBASE + (kt & 1)*KF_B;
        unsigned sVh = VBASE + (kt & 1)*2*VT_B;
        unsigned sVl = sVh + VT_B;

        float s[8][4];
        #pragma unroll
        for (int i = 0; i < 8; i++)
            #pragma unroll
            for (int j = 0; j < 4; j++) s[i][j] = 0.f;

        #pragma unroll
        for (int kc = 0; kc < 9; kc++) {
            unsigned aQ[4];
            ldsm4(aQ, sQ + ((wm + a_ro)*QSTR + kc*8 + a_co)*4);
            #pragma unroll
            for (int jt = 0; jt < 4; jt++) {
                unsigned bK[4];
                ldsm4(bK, sK + ((jt*16 + b_ro)*QSTR + kc*8 + b_co)*4);
                mmatf32u(s[jt*2],   aQ, &bK[0]);
                mmatf32u(s[jt*2+1], aQ, &bK[2]);
            }
        }

        float tm0 = -3.0e38f, tm1 = -3.0e38f;
        #pragma unroll
        for (int f = 0; f < 8; f++) {
            tm0 = fmaxf(tm0, fmaxf(s[f][0], s[f][1]));
            tm1 = fmaxf(tm1, fmaxf(s[f][2], s[f][3]));
        }
        #pragma unroll
        for (int off = 1; off <= 2; off <<= 1) {
            tm0 = fmaxf(tm0, __shfl_xor_sync(0xffffffffu, tm0, off));
            tm1 = fmaxf(tm1, __shfl_xor_sync(0xffffffffu, tm1, off));
        }
        float nm0 = fmaxf(m0r, tm0), nm1 = fmaxf(m1r, tm1);
        float cf0 = __expf(m0r - nm0), cf1 = __expf(m1r - nm1);
        m0r = nm0; m1r = nm1;

        float rs0 = 0.f, rs1 = 0.f;
        #pragma unroll
        for (int f = 0; f < 8; f++) {
            s[f][0] = __expf(s[f][0] - nm0);
            s[f][1] = __expf(s[f][1] - nm0);
            s[f][2] = __expf(s[f][2] - nm1);
            s[f][3] = __expf(s[f][3] - nm1);
            rs0 += s[f][0] + s[f][1];
            rs1 += s[f][2] + s[f][3];
        }
        #pragma unroll
        for (int off = 1; off <= 2; off <<= 1) {
            rs0 += __shfl_xor_sync(0xffffffffu, rs0, off);
            rs1 += __shfl_xor_sync(0xffffffffu, rs1, off);
        }
        l0r = l0r*cf0 + rs0;
        l1r = l1r*cf1 + rs1;

        #pragma unroll
        for (int i = 0; i < 10; i++) {
            o[i][0] *= cf0; o[i][1] *= cf0;
            o[i][2] *= cf1; o[i][3] *= cf1;
        }

        #pragma unroll
        for (int kc = 0; kc < 4; kc++) {
            float* f0 = s[kc*2];
            float* f1 = s[kc*2+1];
            unsigned aP [4] = { packh2(f0[0], f0[1]), packh2(f0[2], f0[3]),
                                packh2(f1[0], f1[1]), packh2(f1[2], f1[3]) };
            unsigned aPl[4] = { packl2(f0[0], f0[1]), packl2(f0[2], f0[3]),
                                packl2(f1[0], f1[1]), packl2(f1[2], f1[3]) };
            #pragma unroll
            for (int dt = 0; dt < 5; dt++) {
                unsigned vH[4], vL[4];
                ldsm4t(vH, sVh + ((kc*16 + lrow)*88 + dt*16 + lcol)*2);
                ldsm4t(vL, sVl + ((kc*16 + lrow)*88 + dt*16 + lcol)*2);
                mma16816(o[dt*2],   aP,  &vH[0]);
                mma16816(o[dt*2],   aPl, &vH[0]);
                mma16816(o[dt*2],   aP,  &vL[0]);
                mma16816(o[dt*2+1], aP,  &vH[2]);
                mma16816(o[dt*2+1], aPl, &vH[2]);
                mma16816(o[dt*2+1], aP,  &vL[2]);
            }
        }
        __syncthreads();
    }

    float i0 = 1.f / l0r, i1 = 1.f / l1r;
    int r0 = b*SEQ + q0 + wm + (lane >> 2);
    int r1 = r0 + 8;
    int gc = (lane & 3) * 2;
    #pragma unroll
    for (int nt = 0; nt < 9; nt++) {
        int col = nt*8 + gc;
        size_t off0 = (size_t)r0*HID + h*HD + col;
        size_t off1 = (size_t)r1*HID + h*HD + col;
        float2 p0, p1;
        p0.x = tf32r(o[nt][0]*i0); p0.y = tf32r(o[nt][1]*i0);
        p1.x = tf32r(o[nt][2]*i1); p1.y = tf32r(o[nt][3]*i1);
        *(float2*)(attn + off0) = p0;
        *(float2*)(attn + off1) = p1;
    }
}

// ---------------- launcher ---------------------------------------------------
extern "C" void kernel_launch(void* const* d_in, const int* in_sizes, int n_in,
                              void* d_out, int out_size)
{
    const float* x      = (const float*)d_in[0];
    const float* c      = (const float*)d_in[1];
    const float* cosb   = (const float*)d_in[2];
    const float* sinb   = (const float*)d_in[3];
    const float* w_qkv  = (const float*)d_in[4];
    const float* b_qkv  = (const float*)d_in[5];
    const float* w_proj = (const float*)d_in[6];
    const float* b_proj = (const float*)d_in[7];
    const float* w_mlp1 = (const float*)d_in[8];
    const float* b_mlp1 = (const float*)d_in[9];
    const float* w_mlp2 = (const float*)d_in[10];
    const float* b_mlp2 = (const float*)d_in[11];
    const float* w_ada  = (const float*)d_in[12];
    const float* b_ada  = (const float*)d_in[13];
    float* out = (float*)d_out;

    float *qkv, *res32, *attn32, *h32;
    float *wqkvT, *wprojT, *wm1T, *wm2T;
    bf16 *qkvh, *qkvl;
    cudaGetSymbolAddress((void**)&qkv,    g_qkv);
    cudaGetSymbolAddress((void**)&qkvh,   g_qkvh);
    cudaGetSymbolAddress((void**)&qkvl,   g_qkvl);
    cudaGetSymbolAddress((void**)&res32,  g_res32);
    cudaGetSymbolAddress((void**)&attn32, g_attn32);
    cudaGetSymbolAddress((void**)&h32,    g_h32);
    cudaGetSymbolAddress((void**)&wqkvT,  g_wqkvT);
    cudaGetSymbolAddress((void**)&wprojT, g_wprojT);
    cudaGetSymbolAddress((void**)&wm1T,   g_wm1T);
    cudaGetSymbolAddress((void**)&wm2T,   g_wm2T);

    cudaFuncSetAttribute(k_gemm32, cudaFuncAttributeMaxDynamicSharedMemorySize,
                         GSMEM);
    cudaFuncSetAttribute(k_attn_tc, cudaFuncAttributeMaxDynamicSharedMemorySize,
                         ATT_SMEM);

    // #1: weight transpose + tf32 round -> [N][K]
    k_roundwT<<<TQ4, dim3(32, 8)>>>(w_qkv, w_proj, w_mlp1, w_mlp2);
    // #2: adaLN
    k_ada<<<dim3(6*HID/128, BATCH), 128>>>(c, w_ada, b_ada);
    // #3: LN + modulate (msa)
    k_lnmod<<<TOK, 288>>>(x, res32, 0, HID);
    // #4: qkv GEMM  -- ncu capture slot
    k_gemm32<<<dim3(3*HID/128, TOK/128), 256, GSMEM>>>(
        res32, wqkvT, b_qkv, qkv, nullptr,
        TOK, 3*HID, HID, 0, nullptr, 0);
    // #5: fused rope + scale + route (q/k fp32 -> g_h32, v bf16 hi/lo)
    k_ropesplit<<<(int)((size_t)TOK*3*HID/4/256), 256>>>(cosb, sinb);
    // #6: attention (tf32 QK + bf16x3 PV)
    k_attn_tc<<<dim3(SEQ/128, NH, BATCH), 256, ATT_SMEM>>>(h32, qkvh, qkvl,
                                                           attn32);
    // #7: proj GEMM + gated residual
    k_gemm32<<<dim3(HID/128, TOK/128), 256, GSMEM>>>(
        attn32, wprojT, b_proj, out, nullptr,
        TOK, HID, HID, 1, x, 2*HID);
    // #8: LN + modulate (mlp)
    k_lnmod<<<TOK, 288>>>(out, res32, 3*HID, 4*HID);
    // #9: mlp1 GEMM + gelu (overwrites g_h32 -- q/k no longer needed)
    k_gemm32<<<dim3(4*HID/128, TOK/128), 256, GSMEM>>>(
        res32, wm1T, b_mlp1, nullptr, h32,
        TOK, 4*HID, HID, 2, nullptr, 0);
    // #10: mlp2 GEMM + gated residual
    k_gemm32<<<dim3(HID/128, TOK/128), 256, GSMEM>>>(
        h32, wm2T, b_mlp2, out, nullptr,
        TOK, HID, 4*HID, 1, out, 5*HID);
}

// round 16
// speedup vs baseline: 1.2860x; 1.0098x over previous
#include <cuda_runtime.h>
#include <cuda_bf16.h>
#include <math.h>
#include <stdint.h>

#define HID   1152
#define NH    16
#define HD    72
#define TXT   256
#define BATCH 8
#define SEQ   1280
#define TOK   (BATCH*SEQ)   /* 10240 */
#define EPS   1e-6f

typedef __nv_bfloat16 bf16;

extern __shared__ char dynsmem[];

// ---------------- scratch ----------------------------------------------------
__device__ float g_mod [BATCH*6*HID];
__device__ float g_qkv [TOK*3*HID];
__device__ bf16  g_qkvh[TOK*3*HID], g_qkvl[TOK*3*HID];   // only V-part used
__device__ float g_res32 [TOK*HID];
__device__ float g_attn32[TOK*HID];
__device__ float g_h32   [TOK*4*HID];   // doubles as [TOK][2*HID] q/k buffer pre-mlp1
// tf32-rounded, TRANSPOSED weights: [N][K]
__device__ float g_wqkvT[3*HID*HID];
__device__ float g_wprojT[HID*HID];
__device__ float g_wm1T[4*HID*HID];
__device__ float g_wm2T[HID*4*HID];

// ---------------- helpers ----------------------------------------------------
__device__ __forceinline__ float tf32r(float x) {
    unsigned u; asm("cvt.rna.tf32.f32 %0, %1;" : "=r"(u) : "f"(x));
    return __uint_as_float(u);
}
__device__ __forceinline__ void split1(float x, bf16 &h, bf16 &l) {
    h = __float2bfloat16_rn(x);
    l = __float2bfloat16_rn(x - __bfloat162float(h));
}
__device__ __forceinline__ unsigned packh2(float a, float b) {
    __nv_bfloat16 ha = __float2bfloat16_rn(a), hb = __float2bfloat16_rn(b);
    return (unsigned)__bfloat16_as_ushort(ha) |
           ((unsigned)__bfloat16_as_ushort(hb) << 16);
}
__device__ __forceinline__ unsigned packl2(float a, float b) {
    float ra = a - __bfloat162float(__float2bfloat16_rn(a));
    float rb = b - __bfloat162float(__float2bfloat16_rn(b));
    return packh2(ra, rb);
}
__device__ __forceinline__ unsigned su32(const void* p) {
    return (unsigned)__cvta_generic_to_shared(p);
}
__device__ __forceinline__ void cp16(unsigned dst, const void* src) {
    asm volatile("cp.async.ca.shared.global [%0],[%1],16;\n" :: "r"(dst), "l"(src));
}
__device__ __forceinline__ void cp16cg(unsigned dst, const void* src) {
    asm volatile("cp.async.cg.shared.global [%0],[%1],16;\n" :: "r"(dst), "l"(src));
}
__device__ __forceinline__ void cpcommit() {
    asm volatile("cp.async.commit_group;\n");
}
template<int N_> __device__ __forceinline__ void cpwait() {
    asm volatile("cp.async.wait_group %0;\n" :: "n"(N_));
}
__device__ __forceinline__ void ldsm4(unsigned* r, unsigned a)
{
    asm volatile("ldmatrix.sync.aligned.m8n8.x4.shared.b16 {%0,%1,%2,%3},[%4];\n"
                 : "=r"(r[0]), "=r"(r[1]), "=r"(r[2]), "=r"(r[3]) : "r"(a));
}
__device__ __forceinline__ void ldsm4t(unsigned* r, unsigned a)
{
    asm volatile("ldmatrix.sync.aligned.m8n8.x4.trans.shared.b16 {%0,%1,%2,%3},[%4];\n"
                 : "=r"(r[0]), "=r"(r[1]), "=r"(r[2]), "=r"(r[3]) : "r"(a));
}
__device__ __forceinline__ void mma16816(float* c, const unsigned* a, const unsigned* b)
{
    asm volatile("mma.sync.aligned.m16n8k16.row.col.f32.bf16.bf16.f32 "
                 "{%0,%1,%2,%3},{%4,%5,%6,%7},{%8,%9},{%0,%1,%2,%3};\n"
                 : "+f"(c[0]), "+f"(c[1]), "+f"(c[2]), "+f"(c[3])
                 : "r"(a[0]), "r"(a[1]), "r"(a[2]), "r"(a[3]),
                   "r"(b[0]), "r"(b[1]));
}
__device__ __forceinline__ void mmatf32u(float* c, const unsigned* a, const unsigned* b)
{
    asm volatile("mma.sync.aligned.m16n8k8.row.col.f32.tf32.tf32.f32 "
                 "{%0,%1,%2,%3},{%4,%5,%6,%7},{%8,%9},{%0,%1,%2,%3};\n"
                 : "+f"(c[0]), "+f"(c[1]), "+f"(c[2]), "+f"(c[3])
                 : "r"(a[0]), "r"(a[1]), "r"(a[2]), "r"(a[3]),
                   "r"(b[0]), "r"(b[1]));
}
__device__ __forceinline__ float gelu_tanh(float t) {
    return 0.5f*t*(1.f + tanhf(0.7978845608028654f*(t + 0.044715f*t*t*t)));
}

// ---------------- merged weight transpose + tf32 round -----------------------
#define TQ1 ((3*HID/32)*(HID/32))
#define TQ2 (TQ1 + (HID/32)*(HID/32))
#define TQ3 (TQ2 + (4*HID/32)*(HID/32))
#define TQ4 (TQ3 + (HID/32)*(4*HID/32))
__global__ void k_roundwT(const float* __restrict__ w_qkv,
                          const float* __restrict__ w_proj,
                          const float* __restrict__ w_mlp1,
                          const float* __restrict__ w_mlp2)
{
    __shared__ float tile[32][33];
    int bid = blockIdx.x;
    const float* src; float* dst; int K, N, li;
    if (bid < TQ1)      { src = w_qkv;  dst = g_wqkvT;  K = HID;   N = 3*HID; li = bid; }
    else if (bid < TQ2) { src = w_proj; dst = g_wprojT; K = HID;   N = HID;   li = bid - TQ1; }
    else if (bid < TQ3) { src = w_mlp1; dst = g_wm1T;   K = HID;   N = 4*HID; li = bid - TQ2; }
    else                { src = w_mlp2; dst = g_wm2T;   K = 4*HID; N = HID;   li = bid - TQ3; }
    int ntN = N / 32;
    int nb = (li % ntN) * 32, kb = (li / ntN) * 32;
    int tx = threadIdx.x, ty = threadIdx.y;
    #pragma unroll
    for (int i = 0; i < 4; i++)
        tile[ty + i*8][tx] = src[(size_t)(kb + ty + i*8)*N + nb + tx];
    __syncthreads();
    #pragma unroll
    for (int i = 0; i < 4; i++)
        dst[(size_t)(nb + ty + i*8)*K + kb + tx] = tf32r(tile[tx][ty + i*8]);
}

// ---------------- adaLN ------------------------------------------------------
__global__ void k_ada(const float* __restrict__ c,
                      const float* __restrict__ w,
                      const float* __restrict__ bias)
{
    __shared__ float sc[HID];
    int b = blockIdx.y;
    for (int i = threadIdx.x; i < HID; i += blockDim.x) {
        float v = c[b*HID + i];
        sc[i] = v / (1.f + __expf(-v));
    }
    __syncthreads();
    int n = blockIdx.x*128 + threadIdx.x;
    float acc = bias[n];
    #pragma unroll 4
    for (int k = 0; k < HID; k++) acc += sc[k] * w[(size_t)k*(6*HID) + n];
    g_mod[b*6*HID + n] = acc;
}

// ---------------- fused LN + modulate, writes tf32-rounded fp32 --------------
__global__ void k_lnmod(const float* __restrict__ x, float* __restrict__ o32,
                        int shofs, int scofs)
{
    int row = blockIdx.x;
    int b   = row / SEQ;
    int t   = threadIdx.x;
    float4 v = ((const float4*)(x + (size_t)row*HID))[t];
    float s  = v.x + v.y + v.z + v.w;
    float ss = v.x*v.x + v.y*v.y + v.z*v.z + v.w*v.w;
    #pragma unroll
    for (int off = 16; off >= 1; off >>= 1) {
        s  += __shfl_xor_sync(0xffffffffu, s , off);
        ss += __shfl_xor_sync(0xffffffffu, ss, off);
    }
    __shared__ float rs[9], rss[9];
    __shared__ float smu, srs;
    if ((t & 31) == 0) { rs[t>>5] = s; rss[t>>5] = ss; }
    __syncthreads();
    if (t == 0) {
        float S = 0.f, SS = 0.f;
        #pragma unroll
        for (int i = 0; i < 9; i++) { S += rs[i]; SS += rss[i]; }
        float mu  = S * (1.f/(float)HID);
        float var = SS * (1.f/(float)HID) - mu*mu;
        smu = mu; srs = rsqrtf(var + EPS);
    }
    __syncthreads();
    float mu = smu, r = srs;
    float4 sh = ((const float4*)(g_mod + b*6*HID + shofs))[t];
    float4 sc = ((const float4*)(g_mod + b*6*HID + scofs))[t];
    float4 o;
    o.x = tf32r((1.f+sc.x)*((v.x-mu)*r) + sh.x);
    o.y = tf32r((1.f+sc.y)*((v.y-mu)*r) + sh.y);
    o.z = tf32r((1.f+sc.z)*((v.z-mu)*r) + sh.z);
    o.w = tf32r((1.f+sc.w)*((v.w-mu)*r) + sh.w);
    ((float4*)(o32 + (size_t)row*HID))[t] = o;
}

// ---------------- tf32 GEMM: deferred cpwait with correct barrier (R15) ------
#define BKF 32
#define APADF 36
#define BPADF 36
#define SMAF (128*APADF)
#define SMBF (128*BPADF)
#define GSMEM (3*(SMAF+SMBF)*4)
__global__ __launch_bounds__(256, 2)
void k_gemm32(const float* __restrict__ A, const float* __restrict__ B,
              const float* __restrict__ bias,
              float* C, float* C2,
              int M, int N, int K, int mode, const float* xres, int gofs)
{
    float* smem = (float*)dynsmem;
    const int t    = threadIdx.x;
    const int lane = t & 31;
    const int wid  = t >> 5;
    const int m0   = blockIdx.y * 128;
    const int n0   = blockIdx.x * 128;
    const int wm   = (wid >> 2) * 64;
    const int wn   = (wid & 3) * 32;
    const int lq   = lane >> 2;
    const int lm   = lane & 3;

    const int a_ro = (lane & 7) + ((lane >> 3) & 1) * 8;
    const int a_co = (lane >> 4) * 4;
    const int b_ro = (lane & 7) + ((lane >> 4) & 1) * 8;
    const int b_co = ((lane >> 3) & 1) * 4;

    float acc[4][4][4];
    #pragma unroll
    for (int i = 0; i < 4; i++)
        #pragma unroll
        for (int j = 0; j < 4; j++)
            #pragma unroll
            for (int q = 0; q < 4; q++) acc[i][j][q] = 0.f;

    const int nIter = K / BKF;

    auto issue = [&](int it, int s) {
        float* as = smem + s*(SMAF + SMBF);
        float* bs = as + SMAF;
        int k0 = it * BKF;
        #pragma unroll
        for (int j = 0; j < 4; j++) {
            int cch = t + j*256;
            int r = cch >> 3, c4 = (cch & 7)*4;
            cp16cg(su32(as + r*APADF + c4), A + (size_t)(m0 + r)*K + k0 + c4);
        }
        #pragma unroll
        for (int j = 0; j < 4; j++) {
            int cch = t + j*256;
            int r = cch >> 3, c4 = (cch & 7)*4;
            cp16cg(su32(bs + r*BPADF + c4), B + (size_t)(n0 + r)*K + k0 + c4);
        }
        cpcommit();
    };

    issue(0, 0);
    issue(1, 1);

    unsigned af[2][4][4], bfr[2][2][4];

    // prologue: group 0 complete + barrier -> preload iter0 ks=0 frags
    cpwait<1>();
    __syncthreads();
    {
        float* as = smem;
        float* bs = as + SMAF;
        #pragma unroll
        for (int mt = 0; mt < 4; mt++)
            ldsm4(af[0][mt], su32(as + (wm + mt*16 + a_ro)*APADF + a_co));
        #pragma unroll
        for (int bt = 0; bt < 2; bt++)
            ldsm4(bfr[0][bt], su32(bs + (wn + bt*16 + b_ro)*BPADF + b_co));
    }

    for (int it = 0; it < nIter; it++) {
        if (it + 2 < nIter) issue(it + 2, (it + 2) % 3);

        float* as  = smem + (it % 3)*(SMAF + SMBF);
        float* bs  = as + SMAF;
        float* asN = smem + ((it + 1) % 3)*(SMAF + SMBF);
        float* bsN = asN + SMAF;

        #pragma unroll
        for (int s8 = 0; s8 < 3; s8++) {
            int cur = s8 & 1, nxt = cur ^ 1;
            int ks = (s8 + 1) * 8;
            #pragma unroll
            for (int mt = 0; mt < 4; mt++)
                ldsm4(af[nxt][mt],
                      su32(as + (wm + mt*16 + a_ro)*APADF + ks + a_co));
            #pragma unroll
            for (int bt = 0; bt < 2; bt++)
                ldsm4(bfr[nxt][bt],
                      su32(bs + (wn + bt*16 + b_ro)*BPADF + ks + b_co));
            #pragma unroll
            for (int mt = 0; mt < 4; mt++)
                #pragma unroll
                for (int bt = 0; bt < 2; bt++) {
                    mmatf32u(acc[mt][bt*2],   af[cur][mt], &bfr[cur][bt][0]);
                    mmatf32u(acc[mt][bt*2+1], af[cur][mt], &bfr[cur][bt][2]);
                }
        }

        if (it + 2 < nIter) cpwait<1>(); else cpwait<0>();
        __syncthreads();

        {
            if (it + 1 < nIter) {
                #pragma unroll
                for (int mt = 0; mt < 4; mt++)
                    ldsm4(af[0][mt],
                          su32(asN + (wm + mt*16 + a_ro)*APADF + a_co));
                #pragma unroll
                for (int bt = 0; bt < 2; bt++)
                    ldsm4(bfr[0][bt],
                          su32(bsN + (wn + bt*16 + b_ro)*BPADF + b_co));
            }
            #pragma unroll
            for (int mt = 0; mt < 4; mt++)
                #pragma unroll
                for (int bt = 0; bt < 2; bt++) {
                    mmatf32u(acc[mt][bt*2],   af[1][mt], &bfr[1][bt][0]);
                    mmatf32u(acc[mt][bt*2+1], af[1][mt], &bfr[1][bt][2]);
                }
        }
    }

    // epilogue
    #pragma unroll
    for (int mt = 0; mt < 4; mt++) {
        #pragma unroll
        for (int half = 0; half < 2; half++) {
            int row = m0 + wm + mt*16 + lq + half*8;
            int bq  = row / SEQ;
            #pragma unroll
            for (int nt = 0; nt < 4; nt++) {
                int col = n0 + wn + nt*8 + lm*2;
                float2 bb = *(const float2*)(bias + col);
                float v0 = acc[mt][nt][half*2+0] + bb.x;
                float v1 = acc[mt][nt][half*2+1] + bb.y;
                if (mode == 1) {
                    float2 g  = *(const float2*)(g_mod + bq*6*HID + gofs + col);
                    float2 xr = *(const float2*)(xres + (size_t)row*N + col);
                    float2 o; o.x = xr.x + g.x*v0; o.y = xr.y + g.y*v1;
                    *(float2*)(C + (size_t)row*N + col) = o;
                } else if (mode == 2) {
                    float2 o;
                    o.x = tf32r(gelu_tanh(v0));
                    o.y = tf32r(gelu_tanh(v1));
                    *(float2*)(C2 + (size_t)row*N + col) = o;
                } else {
                    float2 o; o.x = v0; o.y = v1;
                    *(float2*)(C + (size_t)row*N + col) = o;
                }
            }
        }
    }
}

// ---------------- fused RoPE + scale + route ---------------------------------
__global__ void k_ropesplit(const float* __restrict__ cosb,
                            const float* __restrict__ sinb)
{
    const float scale = 0.11785113019775793f;
    size_t i = (size_t)blockIdx.x*256 + threadIdx.x;
    size_t e = i*4;
    int row = (int)(e / (3*HID));
    int col = (int)(e % (3*HID));
    int pos = row % SEQ;
    int seg = col / HID;
    int inc = col % HID;
    int d   = inc % HD;

    float4 v = ((const float4*)g_qkv)[i];
    float o[4] = {v.x, v.y, v.z, v.w};

    if (seg < 2 && pos >= TXT) {
        int p = pos - TXT;
        if (d < 36) {
            float4 v2 = *(const float4*)(g_qkv + e + 36);
            float w2[4] = {v2.x, v2.y, v2.z, v2.w};
            #pragma unroll
            for (int j = 0; j < 4; j++) {
                float cv = cosb[p*36 + d + j], sv = sinb[p*36 + d + j];
                o[j] = o[j]*cv - w2[j]*sv;
            }
        } else {
            float4 v1 = *(const float4*)(g_qkv + e - 36);
            float w1[4] = {v1.x, v1.y, v1.z, v1.w};
            #pragma unroll
            for (int j = 0; j < 4; j++) {
                float cv = cosb[p*36 + d - 36 + j], sv = sinb[p*36 + d - 36 + j];
                o[j] = w1[j]*sv + o[j]*cv;
            }
        }
    }
    if (seg == 0) {
        #pragma unroll
        for (int j = 0; j < 4; j++) o[j] *= scale;
    }
    if (seg < 2) {
        float4 w;
        w.x = tf32r(o[0]); w.y = tf32r(o[1]);
        w.z = tf32r(o[2]); w.w = tf32r(o[3]);
        *(float4*)(g_h32 + (size_t)row*(2*HID) + seg*HID + inc) = w;
    } else {
        bf16 hh[4], ll[4];
        split1(o[0], hh[0], ll[0]); split1(o[1], hh[1], ll[1]);
        split1(o[2], hh[2], ll[2]); split1(o[3], hh[3], ll[3]);
        ((uint2*)g_qkvh)[i] = *(uint2*)hh;
        ((uint2*)g_qkvl)[i] = *(uint2*)ll;
    }
}

// ---------------- flash attention: tf32 QK^T + bf16x3 PV, KV-tile 128 --------
#define QSTR    76
#define QF_B    (128*QSTR*4)               /* 38912 */
#define KF_B    (128*QSTR*4)               /* 38912 (128-row K tile) */
#define VT_B    (128*88*2)                 /* 22528 (128-row V tile, hi or lo) */
#define ATT_SMEM (QF_B + 2*KF_B + 2*2*VT_B) /* 206848 */
__global__ __launch_bounds__(256)
void k_attn_tc(const float* __restrict__ qk,
               const bf16* __restrict__ vh, const bf16* __restrict__ vl,
               float* __restrict__ attn)
{
    char* smem = dynsmem;
    const unsigned sb    = su32(smem);
    const unsigned sQ    = sb;
    const unsigned KBASE = sb + QF_B;
    const unsigned VBASE = sb + QF_B + 2*KF_B;

    const int t    = threadIdx.x;
    const int lane = t & 31;
    const int wid  = t >> 5;
    const int q0   = blockIdx.x * 128;
    const int h    = blockIdx.y;
    const int b    = blockIdx.z;
    const int wm   = wid * 16;
    const int lrow = lane & 15;
    const int lcol = (lane >> 4) * 8;

    const int a_ro = (lane & 7) + ((lane >> 3) & 1) * 8;
    const int a_co = (lane >> 4) * 4;
    const int b_ro = (lane & 7) + ((lane >> 4) & 1) * 8;
    const int b_co = ((lane >> 3) & 1) * 4;

    // zero smem (stride loop: ATT_SMEM/16 not divisible by 256)
    for (int i = t; i < ATT_SMEM/16; i += 256) {
        uint4 z = {0,0,0,0};
        *(uint4*)(smem + i*16) = z;
    }
    __syncthreads();

    // stage Q: 128 rows x 18 cp16 (fp32) = 2304
    {
        #pragma unroll
        for (int rep = 0; rep < 9; rep++) {
            int id  = rep*256 + t;
            int row = id / 18, c = id % 18;
            const float* src = qk + (size_t)(b*SEQ + q0 + row)*(2*HID) + h*HD + c*4;
            cp16(sQ + row*(QSTR*4) + c*16, src);
        }
        cpcommit();
    }

    // stage K (fp32, 128 rows x 18) + V hi/lo (bf16, 2 x 128 x 9): 4608 cp16
    auto stage_kv = [&](int kt, int s) {
        unsigned sK  = KBASE + s*KF_B;
        unsigned sVh = VBASE + s*2*VT_B;
        unsigned sVl = sVh + VT_B;
        #pragma unroll
        for (int rep = 0; rep < 18; rep++) {
            int id = rep*256 + t;            // 0..4607
            if (id < 2304) {                 // K fp32: 128 rows x 18
                int row = id / 18, c = id % 18;
                const float* src = qk + (size_t)(b*SEQ + kt*128 + row)*(2*HID)
                                 + HID + h*HD + c*4;
                cp16(sK + row*(QSTR*4) + c*16, src);
            } else {                          // V bf16 hi/lo: 2 x 128 x 9
                int id2 = id - 2304;
                int op  = id2 / 1152;
                int rid = id2 % 1152;
                int row = rid / 9, c8 = rid % 9;
                const bf16* src = (op ? vl : vh)
                    + (size_t)(b*SEQ + kt*128 + row)*(3*HID) + 2*HID + h*HD + c8*8;
                cp16((op ? sVl : sVh) + (row*88 + c8*8)*2, src);
            }
        }
        cpcommit();
    };

    stage_kv(0, 0);

    float m0r = -3.0e38f, m1r = -3.0e38f, l0r = 0.f, l1r = 0.f;
    float o[10][4];
    #pragma unroll
    for (int i = 0; i < 10; i++)
        #pragma unroll
        for (int j = 0; j < 4; j++) o[i][j] = 0.f;

    const int NKV = SEQ/128;   // 10 tiles
    for (int kt = 0; kt < NKV; kt++) {
        cpwait<0>();
        __syncthreads();
        if (kt + 1 < NKV) stage_kv(kt + 1, (kt + 1) & 1);

        unsigned sK  = KBASE + (kt & 1)*KF_B;
        unsigned sVh = VBASE + (kt & 1)*2*VT_B;
        unsigned sVl = sVh + VT_B;

        // ---- S = Q K^T in tf32 over 128 kv cols (16 n8-frags) ----
        float s[16][4];
        #pragma unroll
        for (int i = 0; i < 16; i++)
            #pragma unroll
            for (int j = 0; j < 4; j++) s[i][j] = 0.f;

        #pragma unroll
        for (int kc = 0; kc < 9; kc++) {
            unsigned aQ[4];
            ldsm4(aQ, sQ + ((wm + a_ro)*QSTR + kc*8 + a_co)*4);
            #pragma unroll
            for (int jt = 0; jt < 8; jt++) {
                unsigned bK[4];
                ldsm4(bK, sK + ((jt*16 + b_ro)*QSTR + kc*8 + b_co)*4);
                mmatf32u(s[jt*2],   aQ, &bK[0]);
                mmatf32u(s[jt*2+1], aQ, &bK[2]);
            }
        }

        // ---- online softmax (rows lq and lq+8 per warp) ----
        float tm0 = -3.0e38f, tm1 = -3.0e38f;
        #pragma unroll
        for (int f = 0; f < 16; f++) {
            tm0 = fmaxf(tm0, fmaxf(s[f][0], s[f][1]));
            tm1 = fmaxf(tm1, fmaxf(s[f][2], s[f][3]));
        }
        #pragma unroll
        for (int off = 1; off <= 2; off <<= 1) {
            tm0 = fmaxf(tm0, __shfl_xor_sync(0xffffffffu, tm0, off));
            tm1 = fmaxf(tm1, __shfl_xor_sync(0xffffffffu, tm1, off));
        }
        float nm0 = fmaxf(m0r, tm0), nm1 = fmaxf(m1r, tm1);
        float cf0 = __expf(m0r - nm0), cf1 = __expf(m1r - nm1);
        m0r = nm0; m1r = nm1;

        float rs0 = 0.f, rs1 = 0.f;
        #pragma unroll
        for (int f = 0; f < 16; f++) {
            s[f][0] = __expf(s[f][0] - nm0);
            s[f][1] = __expf(s[f][1] - nm0);
            s[f][2] = __expf(s[f][2] - nm1);
            s[f][3] = __expf(s[f][3] - nm1);
            rs0 += s[f][0] + s[f][1];
            rs1 += s[f][2] + s[f][3];
        }
        #pragma unroll
        for (int off = 1; off <= 2; off <<= 1) {
            rs0 += __shfl_xor_sync(0xffffffffu, rs0, off);
            rs1 += __shfl_xor_sync(0xffffffffu, rs1, off);
        }
        l0r = l0r*cf0 + rs0;
        l1r = l1r*cf1 + rs1;

        #pragma unroll
        for (int i = 0; i < 10; i++) {
            o[i][0] *= cf0; o[i][1] *= cf0;
            o[i][2] *= cf1; o[i][3] *= cf1;
        }

        // ---- O += P V (bf16x3) over 8 k16-chunks ----
        #pragma unroll
        for (int kc = 0; kc < 8; kc++) {
            float* f0 = s[kc*2];
            float* f1 = s[kc*2+1];
            unsigned aP [4] = { packh2(f0[0], f0[1]), packh2(f0[2], f0[3]),
                                packh2(f1[0], f1[1]), packh2(f1[2], f1[3]) };
            unsigned aPl[4] = { packl2(f0[0], f0[1]), packl2(f0[2], f0[3]),
                                packl2(f1[0], f1[1]), packl2(f1[2], f1[3]) };
            #pragma unroll
            for (int dt = 0; dt < 5; dt++) {
                unsigned vH[4], vL[4];
                ldsm4t(vH, sVh + ((kc*16 + lrow)*88 + dt*16 + lcol)*2);
                ldsm4t(vL, sVl + ((kc*16 + lrow)*88 + dt*16 + lcol)*2);
                mma16816(o[dt*2],   aP,  &vH[0]);
                mma16816(o[dt*2],   aPl, &vH[0]);
                mma16816(o[dt*2],   aP,  &vL[0]);
                mma16816(o[dt*2+1], aP,  &vH[2]);
                mma16816(o[dt*2+1], aPl, &vH[2]);
                mma16816(o[dt*2+1], aP,  &vL[2]);
            }
        }
        __syncthreads();
    }

    float i0 = 1.f / l0r, i1 = 1.f / l1r;
    int r0 = b*SEQ + q0 + wm + (lane >> 2);
    int r1 = r0 + 8;
    int gc = (lane & 3) * 2;
    #pragma unroll
    for (int nt = 0; nt < 9; nt++) {
        int col = nt*8 + gc;
        size_t off0 = (size_t)r0*HID + h*HD + col;
        size_t off1 = (size_t)r1*HID + h*HD + col;
        float2 p0, p1;
        p0.x = tf32r(o[nt][0]*i0); p0.y = tf32r(o[nt][1]*i0);
        p1.x = tf32r(o[nt][2]*i1); p1.y = tf32r(o[nt][3]*i1);
        *(float2*)(attn + off0) = p0;
        *(float2*)(attn + off1) = p1;
    }
}

// ---------------- launcher ---------------------------------------------------
extern "C" void kernel_launch(void* const* d_in, const int* in_sizes, int n_in,
                              void* d_out, int out_size)
{
    const float* x      = (const float*)d_in[0];
    const float* c      = (const float*)d_in[1];
    const float* cosb   = (const float*)d_in[2];
    const float* sinb   = (const float*)d_in[3];
    const float* w_qkv  = (const float*)d_in[4];
    const float* b_qkv  = (const float*)d_in[5];
    const float* w_proj = (const float*)d_in[6];
    const float* b_proj = (const float*)d_in[7];
    const float* w_mlp1 = (const float*)d_in[8];
    const float* b_mlp1 = (const float*)d_in[9];
    const float* w_mlp2 = (const float*)d_in[10];
    const float* b_mlp2 = (const float*)d_in[11];
    const float* w_ada  = (const float*)d_in[12];
    const float* b_ada  = (const float*)d_in[13];
    float* out = (float*)d_out;

    float *qkv, *res32, *attn32, *h32;
    float *wqkvT, *wprojT, *wm1T, *wm2T;
    bf16 *qkvh, *qkvl;
    cudaGetSymbolAddress((void**)&qkv,    g_qkv);
    cudaGetSymbolAddress((void**)&qkvh,   g_qkvh);
    cudaGetSymbolAddress((void**)&qkvl,   g_qkvl);
    cudaGetSymbolAddress((void**)&res32,  g_res32);
    cudaGetSymbolAddress((void**)&attn32, g_attn32);
    cudaGetSymbolAddress((void**)&h32,    g_h32);
    cudaGetSymbolAddress((void**)&wqkvT,  g_wqkvT);
    cudaGetSymbolAddress((void**)&wprojT, g_wprojT);
    cudaGetSymbolAddress((void**)&wm1T,   g_wm1T);
    cudaGetSymbolAddress((void**)&wm2T,   g_wm2T);

    cudaFuncSetAttribute(k_gemm32, cudaFuncAttributeMaxDynamicSharedMemorySize,
                         GSMEM);
    cudaFuncSetAttribute(k_attn_tc, cudaFuncAttributeMaxDynamicSharedMemorySize,
                         ATT_SMEM);

    // #1: weight transpose + tf32 round -> [N][K]
    k_roundwT<<<TQ4, dim3(32, 8)>>>(w_qkv, w_proj, w_mlp1, w_mlp2);
    // #2: adaLN
    k_ada<<<dim3(6*HID/128, BATCH), 128>>>(c, w_ada, b_ada);
    // #3: LN + modulate (msa)
    k_lnmod<<<TOK, 288>>>(x, res32, 0, HID);
    // #4: qkv GEMM  -- ncu capture slot
    k_gemm32<<<dim3(3*HID/128, TOK/128), 256, GSMEM>>>(
        res32, wqkvT, b_qkv, qkv, nullptr,
        TOK, 3*HID, HID, 0, nullptr, 0);
    // #5: fused rope + scale + route (q/k fp32 -> g_h32, v bf16 hi/lo)
    k_ropesplit<<<(int)((size_t)TOK*3*HID/4/256), 256>>>(cosb, sinb);
    // #6: attention (tf32 QK + bf16x3 PV, KV-tile 128)
    k_attn_tc<<<dim3(SEQ/128, NH, BATCH), 256, ATT_SMEM>>>(h32, qkvh, qkvl,
                                                           attn32);
    // #7: proj GEMM + gated residual
    k_gemm32<<<dim3(HID/128, TOK/128), 256, GSMEM>>>(
        attn32, wprojT, b_proj, out, nullptr,
        TOK, HID, HID, 1, x, 2*HID);
    // #8: LN + modulate (mlp)
    k_lnmod<<<TOK, 288>>>(out, res32, 3*HID, 4*HID);
    // #9: mlp1 GEMM + gelu (overwrites g_h32 -- q/k no longer needed)
    k_gemm32<<<dim3(4*HID/128, TOK/128), 256, GSMEM>>>(
        res32, wm1T, b_mlp1, nullptr, h32,
        TOK, 4*HID, HID, 2, nullptr, 0);
    // #10: mlp2 GEMM + gated residual
    k_gemm32<<<dim3(HID/128, TOK/128), 256, GSMEM>>>(
        h32, wm2T, b_mlp2, out, nullptr,
        TOK, HID, 4*HID, 1, out, 5*HID);
}

// round 17
// speedup vs baseline: 1.3101x; 1.0187x over previous
#include <cuda_runtime.h>
#include <cuda_bf16.h>
#include <math.h>
#include <stdint.h>

#define HID   1152
#define NH    16
#define HD    72
#define TXT   256
#define BATCH 8
#define SEQ   1280
#define TOK   (BATCH*SEQ)   /* 10240 */
#define EPS   1e-6f

typedef __nv_bfloat16 bf16;

extern __shared__ char dynsmem[];

// ---------------- scratch ----------------------------------------------------
__device__ float g_mod [BATCH*6*HID];
__device__ float g_qkv [TOK*3*HID];     // also reused as mlp2 split-K partials
__device__ bf16  g_qkvh[TOK*3*HID], g_qkvl[TOK*3*HID];   // only V-part used
__device__ float g_res32 [TOK*HID];
__device__ float g_attn32[TOK*HID];
__device__ float g_h32   [TOK*4*HID];   // doubles as [TOK][2*HID] q/k buffer pre-mlp1
// tf32-rounded, TRANSPOSED weights: [N][K]
__device__ float g_wqkvT[3*HID*HID];
__device__ float g_wprojT[HID*HID];
__device__ float g_wm1T[4*HID*HID];
__device__ float g_wm2T[HID*4*HID];

// ---------------- helpers ----------------------------------------------------
__device__ __forceinline__ float tf32r(float x) {
    unsigned u; asm("cvt.rna.tf32.f32 %0, %1;" : "=r"(u) : "f"(x));
    return __uint_as_float(u);
}
__device__ __forceinline__ void split1(float x, bf16 &h, bf16 &l) {
    h = __float2bfloat16_rn(x);
    l = __float2bfloat16_rn(x - __bfloat162float(h));
}
__device__ __forceinline__ unsigned packh2(float a, float b) {
    __nv_bfloat16 ha = __float2bfloat16_rn(a), hb = __float2bfloat16_rn(b);
    return (unsigned)__bfloat16_as_ushort(ha) |
           ((unsigned)__bfloat16_as_ushort(hb) << 16);
}
__device__ __forceinline__ unsigned packl2(float a, float b) {
    float ra = a - __bfloat162float(__float2bfloat16_rn(a));
    float rb = b - __bfloat162float(__float2bfloat16_rn(b));
    return packh2(ra, rb);
}
__device__ __forceinline__ unsigned su32(const void* p) {
    return (unsigned)__cvta_generic_to_shared(p);
}
__device__ __forceinline__ void cp16(unsigned dst, const void* src) {
    asm volatile("cp.async.ca.shared.global [%0],[%1],16;\n" :: "r"(dst), "l"(src));
}
__device__ __forceinline__ void cp16cg(unsigned dst, const void* src) {
    asm volatile("cp.async.cg.shared.global [%0],[%1],16;\n" :: "r"(dst), "l"(src));
}
__device__ __forceinline__ void cpcommit() {
    asm volatile("cp.async.commit_group;\n");
}
template<int N_> __device__ __forceinline__ void cpwait() {
    asm volatile("cp.async.wait_group %0;\n" :: "n"(N_));
}
__device__ __forceinline__ void ldsm4(unsigned* r, unsigned a)
{
    asm volatile("ldmatrix.sync.aligned.m8n8.x4.shared.b16 {%0,%1,%2,%3},[%4];\n"
                 : "=r"(r[0]), "=r"(r[1]), "=r"(r[2]), "=r"(r[3]) : "r"(a));
}
__device__ __forceinline__ void ldsm4t(unsigned* r, unsigned a)
{
    asm volatile("ldmatrix.sync.aligned.m8n8.x4.trans.shared.b16 {%0,%1,%2,%3},[%4];\n"
                 : "=r"(r[0]), "=r"(r[1]), "=r"(r[2]), "=r"(r[3]) : "r"(a));
}
__device__ __forceinline__ void mma16816(float* c, const unsigned* a, const unsigned* b)
{
    asm volatile("mma.sync.aligned.m16n8k16.row.col.f32.bf16.bf16.f32 "
                 "{%0,%1,%2,%3},{%4,%5,%6,%7},{%8,%9},{%0,%1,%2,%3};\n"
                 : "+f"(c[0]), "+f"(c[1]), "+f"(c[2]), "+f"(c[3])
                 : "r"(a[0]), "r"(a[1]), "r"(a[2]), "r"(a[3]),
                   "r"(b[0]), "r"(b[1]));
}
__device__ __forceinline__ void mmatf32u(float* c, const unsigned* a, const unsigned* b)
{
    asm volatile("mma.sync.aligned.m16n8k8.row.col.f32.tf32.tf32.f32 "
                 "{%0,%1,%2,%3},{%4,%5,%6,%7},{%8,%9},{%0,%1,%2,%3};\n"
                 : "+f"(c[0]), "+f"(c[1]), "+f"(c[2]), "+f"(c[3])
                 : "r"(a[0]), "r"(a[1]), "r"(a[2]), "r"(a[3]),
                   "r"(b[0]), "r"(b[1]));
}
__device__ __forceinline__ float gelu_tanh(float t) {
    return 0.5f*t*(1.f + tanhf(0.7978845608028654f*(t + 0.044715f*t*t*t)));
}

// ---------------- merged weight transpose + tf32 round -----------------------
#define TQ1 ((3*HID/32)*(HID/32))
#define TQ2 (TQ1 + (HID/32)*(HID/32))
#define TQ3 (TQ2 + (4*HID/32)*(HID/32))
#define TQ4 (TQ3 + (HID/32)*(4*HID/32))
__global__ void k_roundwT(const float* __restrict__ w_qkv,
                          const float* __restrict__ w_proj,
                          const float* __restrict__ w_mlp1,
                          const float* __restrict__ w_mlp2)
{
    __shared__ float tile[32][33];
    int bid = blockIdx.x;
    const float* src; float* dst; int K, N, li;
    if (bid < TQ1)      { src = w_qkv;  dst = g_wqkvT;  K = HID;   N = 3*HID; li = bid; }
    else if (bid < TQ2) { src = w_proj; dst = g_wprojT; K = HID;   N = HID;   li = bid - TQ1; }
    else if (bid < TQ3) { src = w_mlp1; dst = g_wm1T;   K = HID;   N = 4*HID; li = bid - TQ2; }
    else                { src = w_mlp2; dst = g_wm2T;   K = 4*HID; N = HID;   li = bid - TQ3; }
    int ntN = N / 32;
    int nb = (li % ntN) * 32, kb = (li / ntN) * 32;
    int tx = threadIdx.x, ty = threadIdx.y;
    #pragma unroll
    for (int i = 0; i < 4; i++)
        tile[ty + i*8][tx] = src[(size_t)(kb + ty + i*8)*N + nb + tx];
    __syncthreads();
    #pragma unroll
    for (int i = 0; i < 4; i++)
        dst[(size_t)(nb + ty + i*8)*K + kb + tx] = tf32r(tile[tx][ty + i*8]);
}

// ---------------- adaLN ------------------------------------------------------
__global__ void k_ada(const float* __restrict__ c,
                      const float* __restrict__ w,
                      const float* __restrict__ bias)
{
    __shared__ float sc[HID];
    int b = blockIdx.y;
    for (int i = threadIdx.x; i < HID; i += blockDim.x) {
        float v = c[b*HID + i];
        sc[i] = v / (1.f + __expf(-v));
    }
    __syncthreads();
    int n = blockIdx.x*128 + threadIdx.x;
    float acc = bias[n];
    #pragma unroll 4
    for (int k = 0; k < HID; k++) acc += sc[k] * w[(size_t)k*(6*HID) + n];
    g_mod[b*6*HID + n] = acc;
}

// ---------------- fused LN + modulate, writes tf32-rounded fp32 --------------
__global__ void k_lnmod(const float* __restrict__ x, float* __restrict__ o32,
                        int shofs, int scofs)
{
    int row = blockIdx.x;
    int b   = row / SEQ;
    int t   = threadIdx.x;
    float4 v = ((const float4*)(x + (size_t)row*HID))[t];
    float s  = v.x + v.y + v.z + v.w;
    float ss = v.x*v.x + v.y*v.y + v.z*v.z + v.w*v.w;
    #pragma unroll
    for (int off = 16; off >= 1; off >>= 1) {
        s  += __shfl_xor_sync(0xffffffffu, s , off);
        ss += __shfl_xor_sync(0xffffffffu, ss, off);
    }
    __shared__ float rs[9], rss[9];
    __shared__ float smu, srs;
    if ((t & 31) == 0) { rs[t>>5] = s; rss[t>>5] = ss; }
    __syncthreads();
    if (t == 0) {
        float S = 0.f, SS = 0.f;
        #pragma unroll
        for (int i = 0; i < 9; i++) { S += rs[i]; SS += rss[i]; }
        float mu  = S * (1.f/(float)HID);
        float var = SS * (1.f/(float)HID) - mu*mu;
        smu = mu; srs = rsqrtf(var + EPS);
    }
    __syncthreads();
    float mu = smu, r = srs;
    float4 sh = ((const float4*)(g_mod + b*6*HID + shofs))[t];
    float4 sc = ((const float4*)(g_mod + b*6*HID + scofs))[t];
    float4 o;
    o.x = tf32r((1.f+sc.x)*((v.x-mu)*r) + sh.x);
    o.y = tf32r((1.f+sc.y)*((v.y-mu)*r) + sh.y);
    o.z = tf32r((1.f+sc.z)*((v.z-mu)*r) + sh.z);
    o.w = tf32r((1.f+sc.w)*((v.w-mu)*r) + sh.w);
    ((float4*)(o32 + (size_t)row*HID))[t] = o;
}

// ---------------- tf32 GEMM (R15 schedule) + split-K support -----------------
// K = loop K (elements this CTA accumulates); Kst = row stride of A and B.
// gridDim.z > 1 => split-K: slice z handles k range [z*K, (z+1)*K), and
// mode 3 writes raw partials to C + z*M*N.
// mode 0: C=acc+bias ; 1: C=xres+g*(acc+bias) ; 2: C2=tf32r(gelu(acc+bias)) ;
// mode 3: C=acc (raw, per-slice partial)
#define BKF 32
#define APADF 36
#define BPADF 36
#define SMAF (128*APADF)
#define SMBF (128*BPADF)
#define GSMEM (3*(SMAF+SMBF)*4)
__global__ __launch_bounds__(256, 2)
void k_gemm32(const float* __restrict__ A, const float* __restrict__ B,
              const float* __restrict__ bias,
              float* C, float* C2,
              int M, int N, int K, int Kst, int mode,
              const float* xres, int gofs)
{
    float* smem = (float*)dynsmem;
    const int t    = threadIdx.x;
    const int lane = t & 31;
    const int wid  = t >> 5;
    const int m0   = blockIdx.y * 128;
    const int n0   = blockIdx.x * 128;
    const int wm   = (wid >> 2) * 64;
    const int wn   = (wid & 3) * 32;
    const int lq   = lane >> 2;
    const int lm   = lane & 3;

    // split-K slice offset
    A += (size_t)blockIdx.z * K;
    B += (size_t)blockIdx.z * K;
    C += (size_t)blockIdx.z * M * N * (mode == 3 ? 1 : 0);

    const int a_ro = (lane & 7) + ((lane >> 3) & 1) * 8;
    const int a_co = (lane >> 4) * 4;
    const int b_ro = (lane & 7) + ((lane >> 4) & 1) * 8;
    const int b_co = ((lane >> 3) & 1) * 4;

    float acc[4][4][4];
    #pragma unroll
    for (int i = 0; i < 4; i++)
        #pragma unroll
        for (int j = 0; j < 4; j++)
            #pragma unroll
            for (int q = 0; q < 4; q++) acc[i][j][q] = 0.f;

    const int nIter = K / BKF;

    auto issue = [&](int it, int s) {
        float* as = smem + s*(SMAF + SMBF);
        float* bs = as + SMAF;
        int k0 = it * BKF;
        #pragma unroll
        for (int j = 0; j < 4; j++) {
            int cch = t + j*256;
            int r = cch >> 3, c4 = (cch & 7)*4;
            cp16cg(su32(as + r*APADF + c4), A + (size_t)(m0 + r)*Kst + k0 + c4);
        }
        #pragma unroll
        for (int j = 0; j < 4; j++) {
            int cch = t + j*256;
            int r = cch >> 3, c4 = (cch & 7)*4;
            cp16cg(su32(bs + r*BPADF + c4), B + (size_t)(n0 + r)*Kst + k0 + c4);
        }
        cpcommit();
    };

    issue(0, 0);
    issue(1, 1);

    unsigned af[2][4][4], bfr[2][2][4];

    cpwait<1>();
    __syncthreads();
    {
        float* as = smem;
        float* bs = as + SMAF;
        #pragma unroll
        for (int mt = 0; mt < 4; mt++)
            ldsm4(af[0][mt], su32(as + (wm + mt*16 + a_ro)*APADF + a_co));
        #pragma unroll
        for (int bt = 0; bt < 2; bt++)
            ldsm4(bfr[0][bt], su32(bs + (wn + bt*16 + b_ro)*BPADF + b_co));
    }

    for (int it = 0; it < nIter; it++) {
        if (it + 2 < nIter) issue(it + 2, (it + 2) % 3);

        float* as  = smem + (it % 3)*(SMAF + SMBF);
        float* bs  = as + SMAF;
        float* asN = smem + ((it + 1) % 3)*(SMAF + SMBF);
        float* bsN = asN + SMAF;

        #pragma unroll
        for (int s8 = 0; s8 < 3; s8++) {
            int cur = s8 & 1, nxt = cur ^ 1;
            int ks = (s8 + 1) * 8;
            #pragma unroll
            for (int mt = 0; mt < 4; mt++)
                ldsm4(af[nxt][mt],
                      su32(as + (wm + mt*16 + a_ro)*APADF + ks + a_co));
            #pragma unroll
            for (int bt = 0; bt < 2; bt++)
                ldsm4(bfr[nxt][bt],
                      su32(bs + (wn + bt*16 + b_ro)*BPADF + ks + b_co));
            #pragma unroll
            for (int mt = 0; mt < 4; mt++)
                #pragma unroll
                for (int bt = 0; bt < 2; bt++) {
                    mmatf32u(acc[mt][bt*2],   af[cur][mt], &bfr[cur][bt][0]);
                    mmatf32u(acc[mt][bt*2+1], af[cur][mt], &bfr[cur][bt][2]);
                }
        }

        if (it + 2 < nIter) cpwait<1>(); else cpwait<0>();
        __syncthreads();

        {
            if (it + 1 < nIter) {
                #pragma unroll
                for (int mt = 0; mt < 4; mt++)
                    ldsm4(af[0][mt],
                          su32(asN + (wm + mt*16 + a_ro)*APADF + a_co));
                #pragma unroll
                for (int bt = 0; bt < 2; bt++)
                    ldsm4(bfr[0][bt],
                          su32(bsN + (wn + bt*16 + b_ro)*BPADF + b_co));
            }
            #pragma unroll
            for (int mt = 0; mt < 4; mt++)
                #pragma unroll
                for (int bt = 0; bt < 2; bt++) {
                    mmatf32u(acc[mt][bt*2],   af[1][mt], &bfr[1][bt][0]);
                    mmatf32u(acc[mt][bt*2+1], af[1][mt], &bfr[1][bt][2]);
                }
        }
    }

    // epilogue
    #pragma unroll
    for (int mt = 0; mt < 4; mt++) {
        #pragma unroll
        for (int half = 0; half < 2; half++) {
            int row = m0 + wm + mt*16 + lq + half*8;
            int bq  = row / SEQ;
            #pragma unroll
            for (int nt = 0; nt < 4; nt++) {
                int col = n0 + wn + nt*8 + lm*2;
                float v0 = acc[mt][nt][half*2+0];
                float v1 = acc[mt][nt][half*2+1];
                if (mode == 3) {
                    float2 o; o.x = v0; o.y = v1;
                    *(float2*)(C + (size_t)row*N + col) = o;
                    continue;
                }
                float2 bb = *(const float2*)(bias + col);
                v0 += bb.x; v1 += bb.y;
                if (mode == 1) {
                    float2 g  = *(const float2*)(g_mod + bq*6*HID + gofs + col);
                    float2 xr = *(const float2*)(xres + (size_t)row*N + col);
                    float2 o; o.x = xr.x + g.x*v0; o.y = xr.y + g.y*v1;
                    *(float2*)(C + (size_t)row*N + col) = o;
                } else if (mode == 2) {
                    float2 o;
                    o.x = tf32r(gelu_tanh(v0));
                    o.y = tf32r(gelu_tanh(v1));
                    *(float2*)(C2 + (size_t)row*N + col) = o;
                } else {
                    float2 o; o.x = v0; o.y = v1;
                    *(float2*)(C + (size_t)row*N + col) = o;
                }
            }
        }
    }
}

// ---------------- split-K reduction + gated residual -------------------------
// out = out + g_mod[bq, gofs+col] * (p0 + p1 + bias)
__global__ void k_red(const float* __restrict__ p,
                      const float* __restrict__ bias,
                      float* __restrict__ out, int gofs)
{
    size_t i = (size_t)blockIdx.x*256 + threadIdx.x;   // float4 index
    size_t e = i*4;
    int row = (int)(e / HID);
    int col = (int)(e % HID);
    int bq  = row / SEQ;
    float4 a  = ((const float4*)p)[i];
    float4 b  = ((const float4*)(p + (size_t)TOK*HID))[i];
    float4 bb = *(const float4*)(bias + col);
    float4 g  = *(const float4*)(g_mod + bq*6*HID + gofs + col);
    float4 xr = ((const float4*)out)[i];
    float4 o;
    o.x = xr.x + g.x*(a.x + b.x + bb.x);
    o.y = xr.y + g.y*(a.y + b.y + bb.y);
    o.z = xr.z + g.z*(a.z + b.z + bb.z);
    o.w = xr.w + g.w*(a.w + b.w + bb.w);
    ((float4*)out)[i] = o;
}

// ---------------- fused RoPE + scale + route ---------------------------------
__global__ void k_ropesplit(const float* __restrict__ cosb,
                            const float* __restrict__ sinb)
{
    const float scale = 0.11785113019775793f;
    size_t i = (size_t)blockIdx.x*256 + threadIdx.x;
    size_t e = i*4;
    int row = (int)(e / (3*HID));
    int col = (int)(e % (3*HID));
    int pos = row % SEQ;
    int seg = col / HID;
    int inc = col % HID;
    int d   = inc % HD;

    float4 v = ((const float4*)g_qkv)[i];
    float o[4] = {v.x, v.y, v.z, v.w};

    if (seg < 2 && pos >= TXT) {
        int p = pos - TXT;
        if (d < 36) {
            float4 v2 = *(const float4*)(g_qkv + e + 36);
            float w2[4] = {v2.x, v2.y, v2.z, v2.w};
            #pragma unroll
            for (int j = 0; j < 4; j++) {
                float cv = cosb[p*36 + d + j], sv = sinb[p*36 + d + j];
                o[j] = o[j]*cv - w2[j]*sv;
            }
        } else {
            float4 v1 = *(const float4*)(g_qkv + e - 36);
            float w1[4] = {v1.x, v1.y, v1.z, v1.w};
            #pragma unroll
            for (int j = 0; j < 4; j++) {
                float cv = cosb[p*36 + d - 36 + j], sv = sinb[p*36 + d - 36 + j];
                o[j] = w1[j]*sv + o[j]*cv;
            }
        }
    }
    if (seg == 0) {
        #pragma unroll
        for (int j = 0; j < 4; j++) o[j] *= scale;
    }
    if (seg < 2) {
        float4 w;
        w.x = tf32r(o[0]); w.y = tf32r(o[1]);
        w.z = tf32r(o[2]); w.w = tf32r(o[3]);
        *(float4*)(g_h32 + (size_t)row*(2*HID) + seg*HID + inc) = w;
    } else {
        bf16 hh[4], ll[4];
        split1(o[0], hh[0], ll[0]); split1(o[1], hh[1], ll[1]);
        split1(o[2], hh[2], ll[2]); split1(o[3], hh[3], ll[3]);
        ((uint2*)g_qkvh)[i] = *(uint2*)hh;
        ((uint2*)g_qkvl)[i] = *(uint2*)ll;
    }
}

// ---------------- flash attention: tf32 QK^T + bf16x3 PV, KV-tile 128 --------
#define QSTR    76
#define QF_B    (128*QSTR*4)
#define KF_B    (128*QSTR*4)
#define VT_B    (128*88*2)
#define ATT_SMEM (QF_B + 2*KF_B + 2*2*VT_B)
__global__ __launch_bounds__(256)
void k_attn_tc(const float* __restrict__ qk,
               const bf16* __restrict__ vh, const bf16* __restrict__ vl,
               float* __restrict__ attn)
{
    char* smem = dynsmem;
    const unsigned sb    = su32(smem);
    const unsigned sQ    = sb;
    const unsigned KBASE = sb + QF_B;
    const unsigned VBASE = sb + QF_B + 2*KF_B;

    const int t    = threadIdx.x;
    const int lane = t & 31;
    const int wid  = t >> 5;
    const int q0   = blockIdx.x * 128;
    const int h    = blockIdx.y;
    const int b    = blockIdx.z;
    const int wm   = wid * 16;
    const int lrow = lane & 15;
    const int lcol = (lane >> 4) * 8;

    const int a_ro = (lane & 7) + ((lane >> 3) & 1) * 8;
    const int a_co = (lane >> 4) * 4;
    const int b_ro = (lane & 7) + ((lane >> 4) & 1) * 8;
    const int b_co = ((lane >> 3) & 1) * 4;

    for (int i = t; i < ATT_SMEM/16; i += 256) {
        uint4 z = {0,0,0,0};
        *(uint4*)(smem + i*16) = z;
    }
    __syncthreads();

    {
        #pragma unroll
        for (int rep = 0; rep < 9; rep++) {
            int id  = rep*256 + t;
            int row = id / 18, c = id % 18;
            const float* src = qk + (size_t)(b*SEQ + q0 + row)*(2*HID) + h*HD + c*4;
            cp16(sQ + row*(QSTR*4) + c*16, src);
        }
        cpcommit();
    }

    auto stage_kv = [&](int kt, int s) {
        unsigned sK  = KBASE + s*KF_B;
        unsigned sVh = VBASE + s*2*VT_B;
        unsigned sVl = sVh + VT_B;
        #pragma unroll
        for (int rep = 0; rep < 18; rep++) {
            int id = rep*256 + t;
            if (id < 2304) {
                int row = id / 18, c = id % 18;
                const float* src = qk + (size_t)(b*SEQ + kt*128 + row)*(2*HID)
                                 + HID + h*HD + c*4;
                cp16(sK + row*(QSTR*4) + c*16, src);
            } else {
                int id2 = id - 2304;
                int op  = id2 / 1152;
                int rid = id2 % 1152;
                int row = rid / 9, c8 = rid % 9;
                const bf16* src = (op ? vl : vh)
                    + (size_t)(b*SEQ + kt*128 + row)*(3*HID) + 2*HID + h*HD + c8*8;
                cp16((op ? sVl : sVh) + (row*88 + c8*8)*2, src);
            }
        }
        cpcommit();
    };

    stage_kv(0, 0);

    float m0r = -3.0e38f, m1r = -3.0e38f, l0r = 0.f, l1r = 0.f;
    float o[10][4];
    #pragma unroll
    for (int i = 0; i < 10; i++)
        #pragma unroll
        for (int j = 0; j < 4; j++) o[i][j] = 0.f;

    const int NKV = SEQ/128;
    for (int kt = 0; kt < NKV; kt++) {
        cpwait<0>();
        __syncthreads();
        if (kt + 1 < NKV) stage_kv(kt + 1, (kt + 1) & 1);

        unsigned sK  = KBASE + (kt & 1)*KF_B;
        unsigned sVh = VBASE + (kt & 1)*2*VT_B;
        unsigned sVl = sVh + VT_B;

        float s[16][4];
        #pragma unroll
        for (int i = 0; i < 16; i++)
            #pragma unroll
            for (int j = 0; j < 4; j++) s[i][j] = 0.f;

        #pragma unroll
        for (int kc = 0; kc < 9; kc++) {
            unsigned aQ[4];
            ldsm4(aQ, sQ + ((wm + a_ro)*QSTR + kc*8 + a_co)*4);
            #pragma unroll
            for (int jt = 0; jt < 8; jt++) {
                unsigned bK[4];
                ldsm4(bK, sK + ((jt*16 + b_ro)*QSTR + kc*8 + b_co)*4);
                mmatf32u(s[jt*2],   aQ, &bK[0]);
                mmatf32u(s[jt*2+1], aQ, &bK[2]);
            }
        }

        float tm0 = -3.0e38f, tm1 = -3.0e38f;
        #pragma unroll
        for (int f = 0; f < 16; f++) {
            tm0 = fmaxf(tm0, fmaxf(s[f][0], s[f][1]));
            tm1 = fmaxf(tm1, fmaxf(s[f][2], s[f][3]));
        }
        #pragma unroll
        for (int off = 1; off <= 2; off <<= 1) {
            tm0 = fmaxf(tm0, __shfl_xor_sync(0xffffffffu, tm0, off));
            tm1 = fmaxf(tm1, __shfl_xor_sync(0xffffffffu, tm1, off));
        }
        float nm0 = fmaxf(m0r, tm0), nm1 = fmaxf(m1r, tm1);
        float cf0 = __expf(m0r - nm0), cf1 = __expf(m1r - nm1);
        m0r = nm0; m1r = nm1;

        float rs0 = 0.f, rs1 = 0.f;
        #pragma unroll
        for (int f = 0; f < 16; f++) {
            s[f][0] = __expf(s[f][0] - nm0);
            s[f][1] = __expf(s[f][1] - nm0);
            s[f][2] = __expf(s[f][2] - nm1);
            s[f][3] = __expf(s[f][3] - nm1);
            rs0 += s[f][0] + s[f][1];
            rs1 += s[f][2] + s[f][3];
        }
        #pragma unroll
        for (int off = 1; off <= 2; off <<= 1) {
            rs0 += __shfl_xor_sync(0xffffffffu, rs0, off);
            rs1 += __shfl_xor_sync(0xffffffffu, rs1, off);
        }
        l0r = l0r*cf0 + rs0;
        l1r = l1r*cf1 + rs1;

        #pragma unroll
        for (int i = 0; i < 10; i++) {
            o[i][0] *= cf0; o[i][1] *= cf0;
            o[i][2] *= cf1; o[i][3] *= cf1;
        }

        #pragma unroll
        for (int kc = 0; kc < 8; kc++) {
            float* f0 = s[kc*2];
            float* f1 = s[kc*2+1];
            unsigned aP [4] = { packh2(f0[0], f0[1]), packh2(f0[2], f0[3]),
                                packh2(f1[0], f1[1]), packh2(f1[2], f1[3]) };
            unsigned aPl[4] = { packl2(f0[0], f0[1]), packl2(f0[2], f0[3]),
                                packl2(f1[0], f1[1]), packl2(f1[2], f1[3]) };
            #pragma unroll
            for (int dt = 0; dt < 5; dt++) {
                unsigned vH[4], vL[4];
                ldsm4t(vH, sVh + ((kc*16 + lrow)*88 + dt*16 + lcol)*2);
                ldsm4t(vL, sVl + ((kc*16 + lrow)*88 + dt*16 + lcol)*2);
                mma16816(o[dt*2],   aP,  &vH[0]);
                mma16816(o[dt*2],   aPl, &vH[0]);
                mma16816(o[dt*2],   aP,  &vL[0]);
                mma16816(o[dt*2+1], aP,  &vH[2]);
                mma16816(o[dt*2+1], aPl, &vH[2]);
                mma16816(o[dt*2+1], aP,  &vL[2]);
            }
        }
        __syncthreads();
    }

    float i0 = 1.f / l0r, i1 = 1.f / l1r;
    int r0 = b*SEQ + q0 + wm + (lane >> 2);
    int r1 = r0 + 8;
    int gc = (lane & 3) * 2;
    #pragma unroll
    for (int nt = 0; nt < 9; nt++) {
        int col = nt*8 + gc;
        size_t off0 = (size_t)r0*HID + h*HD + col;
        size_t off1 = (size_t)r1*HID + h*HD + col;
        float2 p0, p1;
        p0.x = tf32r(o[nt][0]*i0); p0.y = tf32r(o[nt][1]*i0);
        p1.x = tf32r(o[nt][2]*i1); p1.y = tf32r(o[nt][3]*i1);
        *(float2*)(attn + off0) = p0;
        *(float2*)(attn + off1) = p1;
    }
}

// ---------------- launcher ---------------------------------------------------
extern "C" void kernel_launch(void* const* d_in, const int* in_sizes, int n_in,
                              void* d_out, int out_size)
{
    const float* x      = (const float*)d_in[0];
    const float* c      = (const float*)d_in[1];
    const float* cosb   = (const float*)d_in[2];
    const float* sinb   = (const float*)d_in[3];
    const float* w_qkv  = (const float*)d_in[4];
    const float* b_qkv  = (const float*)d_in[5];
    const float* w_proj = (const float*)d_in[6];
    const float* b_proj = (const float*)d_in[7];
    const float* w_mlp1 = (const float*)d_in[8];
    const float* b_mlp1 = (const float*)d_in[9];
    const float* w_mlp2 = (const float*)d_in[10];
    const float* b_mlp2 = (const float*)d_in[11];
    const float* w_ada  = (const float*)d_in[12];
    const float* b_ada  = (const float*)d_in[13];
    float* out = (float*)d_out;

    float *qkv, *res32, *attn32, *h32;
    float *wqkvT, *wprojT, *wm1T, *wm2T;
    bf16 *qkvh, *qkvl;
    cudaGetSymbolAddress((void**)&qkv,    g_qkv);
    cudaGetSymbolAddress((void**)&qkvh,   g_qkvh);
    cudaGetSymbolAddress((void**)&qkvl,   g_qkvl);
    cudaGetSymbolAddress((void**)&res32,  g_res32);
    cudaGetSymbolAddress((void**)&attn32, g_attn32);
    cudaGetSymbolAddress((void**)&h32,    g_h32);
    cudaGetSymbolAddress((void**)&wqkvT,  g_wqkvT);
    cudaGetSymbolAddress((void**)&wprojT, g_wprojT);
    cudaGetSymbolAddress((void**)&wm1T,   g_wm1T);
    cudaGetSymbolAddress((void**)&wm2T,   g_wm2T);

    cudaFuncSetAttribute(k_gemm32, cudaFuncAttributeMaxDynamicSharedMemorySize,
                         GSMEM);
    cudaFuncSetAttribute(k_attn_tc, cudaFuncAttributeMaxDynamicSharedMemorySize,
                         ATT_SMEM);

    // #1: weight transpose + tf32 round -> [N][K]
    k_roundwT<<<TQ4, dim3(32, 8)>>>(w_qkv, w_proj, w_mlp1, w_mlp2);
    // #2: adaLN
    k_ada<<<dim3(6*HID/128, BATCH), 128>>>(c, w_ada, b_ada);
    // #3: LN + modulate (msa)
    k_lnmod<<<TOK, 288>>>(x, res32, 0, HID);
    // #4: qkv GEMM  -- ncu capture slot
    k_gemm32<<<dim3(3*HID/128, TOK/128), 256, GSMEM>>>(
        res32, wqkvT, b_qkv, qkv, nullptr,
        TOK, 3*HID, HID, HID, 0, nullptr, 0);
    // #5: fused rope + scale + route (q/k fp32 -> g_h32, v bf16 hi/lo)
    k_ropesplit<<<(int)((size_t)TOK*3*HID/4/256), 256>>>(cosb, sinb);
    // #6: attention (tf32 QK + bf16x3 PV, KV-tile 128)
    k_attn_tc<<<dim3(SEQ/128, NH, BATCH), 256, ATT_SMEM>>>(h32, qkvh, qkvl,
                                                           attn32);
    // #7: proj GEMM + gated residual
    k_gemm32<<<dim3(HID/128, TOK/128), 256, GSMEM>>>(
        attn32, wprojT, b_proj, out, nullptr,
        TOK, HID, HID, HID, 1, x, 2*HID);
    // #8: LN + modulate (mlp)
    k_lnmod<<<TOK, 288>>>(out, res32, 3*HID, 4*HID);
    // #9: mlp1 GEMM + gelu (overwrites g_h32 -- q/k no longer needed)
    k_gemm32<<<dim3(4*HID/128, TOK/128), 256, GSMEM>>>(
        res32, wm1T, b_mlp1, nullptr, h32,
        TOK, 4*HID, HID, HID, 2, nullptr, 0);
    // #10: mlp2 GEMM, split-K=2, raw partials into g_qkv scratch
    k_gemm32<<<dim3(HID/128, TOK/128, 2), 256, GSMEM>>>(
        h32, wm2T, nullptr, qkv, nullptr,
        TOK, HID, 2*HID, 4*HID, 3, nullptr, 0);
    // #11: reduce partials + bias + gated residual (in-place on out)
    k_red<<<TOK*HID/4/256, 256>>>(qkv, b_mlp2, out, 5*HID);
}